// round 11
// baseline (speedup 1.0000x reference)
#include <cuda_runtime.h>
#include <cstdint>
#include <cmath>

#define BB 2
#define LL 2048
#define DD 2048
#define HH 16
#define DH 128

// ---------------- scratch ----------------
__device__ float    g_q[(size_t)BB * HH * LL * DH];     // fp32 after GEMM, tf32 bits after rope
__device__ float    g_k[(size_t)BB * HH * LL * DH];
__device__ uint32_t g_v[(size_t)BB * HH * LL * DH];     // tf32 bits, TRANSPOSED: [b][h][d][l]
__device__ uint32_t g_attn[(size_t)BB * LL * DD];       // tf32 bits
__device__ uint32_t g_xc[(size_t)BB * LL * DD];         // x as tf32 bits
__device__ uint32_t g_wqc[(size_t)DD * DD];             // W^T as tf32 bits  [n][k]
__device__ uint32_t g_wkc[(size_t)DD * DD];
__device__ uint32_t g_wvc[(size_t)DD * DD];
__device__ uint32_t g_woc[(size_t)DD * DD];
__device__ float    g_invf[64];

__global__ void build_invf_kernel() {
    int i = threadIdx.x;
    if (i < 64) {
        double e = (double)(2 * i) / 128.0;
        g_invf[i] = (float)pow(500000.0, -e);
    }
}

__device__ __forceinline__ uint32_t smem_u32(const void* p) {
    uint32_t a;
    asm("{ .reg .u64 t; cvta.to.shared.u64 t, %1; cvt.u32.u64 %0, t; }"
        : "=r"(a) : "l"(p));
    return a;
}

__device__ __forceinline__ uint32_t f2tf32(float f) {
    uint32_t u;
    asm("cvt.rna.tf32.f32 %0, %1;" : "=r"(u) : "f"(f));
    return u;
}

__device__ __forceinline__ float fast_exp2(float x) {
    float r;
    asm("ex2.approx.ftz.f32 %0, %1;" : "=f"(r) : "f"(x));
    return r;
}

#define MMA_TF32(acc, a0, a1, a2, a3, b0, b1)                                 \
    asm volatile(                                                             \
        "mma.sync.aligned.m16n8k8.row.col.f32.tf32.tf32.f32 "                 \
        "{%0,%1,%2,%3}, {%4,%5,%6,%7}, {%8,%9}, {%0,%1,%2,%3};"               \
        : "+f"((acc)[0]), "+f"((acc)[1]), "+f"((acc)[2]), "+f"((acc)[3])      \
        : "r"(a0), "r"(a1), "r"(a2), "r"(a3), "r"(b0), "r"(b1))

#define LDSM_X4(r0, r1, r2, r3, addr)                                         \
    asm volatile("ldmatrix.sync.aligned.m8n8.x4.shared.b16 {%0,%1,%2,%3}, [%4];" \
                 : "=r"(r0), "=r"(r1), "=r"(r2), "=r"(r3) : "r"(addr))

#define CP_ASYNC16(saddr, gptr)                                               \
    asm volatile("cp.async.cg.shared.global [%0], [%1], 16;"                  \
                 :: "r"(saddr), "l"(gptr))
#define CP_COMMIT() asm volatile("cp.async.commit_group;")
#define CP_WAIT(n)  asm volatile("cp.async.wait_group %0;" :: "n"(n))

// ---------------- fp32 -> tf32-bits converters ----------------
__global__ __launch_bounds__(256)
void cvt_kernel(const float* __restrict__ s, uint32_t* __restrict__ d, int n4)
{
    int i = blockIdx.x * 256 + threadIdx.x;
    if (i < n4) {
        float4 v = ((const float4*)s)[i];
        ((uint4*)d)[i] = make_uint4(f2tf32(v.x), f2tf32(v.y), f2tf32(v.z), f2tf32(v.w));
    }
}

// transpose + convert: W [k][n] fp32 -> Wt [n][k] tf32 bits
__global__ __launch_bounds__(256)
void cvt_t_kernel(const float* __restrict__ s, uint32_t* __restrict__ d)
{
    __shared__ uint32_t tile[32][33];
    const int tx = threadIdx.x & 31, ty = threadIdx.x >> 5;
    const int c0 = blockIdx.x * 32, r0 = blockIdx.y * 32;
#pragma unroll
    for (int i = 0; i < 4; i++)
        tile[ty + i * 8][tx] = f2tf32(s[(size_t)(r0 + ty + i * 8) * DD + c0 + tx]);
    __syncthreads();
#pragma unroll
    for (int i = 0; i < 4; i++)
        d[(size_t)(c0 + ty + i * 8) * DD + r0 + tx] = tile[tx][ty + i * 8];
}

// ============================================================================
// tf32 mma GEMM, ldmatrix feeds: C[M,N] = A[M,K] @ Bt^T  (Bt is [n][k])
// CTA 128x128, 512 threads, 16 warps (4m x 4n), warp tile 32x32.
// ============================================================================
#define ASTRIDE 36
#define A_FLOATS (128 * ASTRIDE)          // 4608
#define B_FLOATS (128 * ASTRIDE)          // 4608
#define BUF_FLOATS (A_FLOATS + B_FLOATS)  // 9216
#define GEMM_SMEM_BYTES (2 * BUF_FLOATS * 4)  // 73728

template <int MODE>
__global__ __launch_bounds__(512, 1)
void mma_gemm_kernel(const uint32_t* __restrict__ A,
                     const uint32_t* __restrict__ B0,
                     const uint32_t* __restrict__ B1,
                     const uint32_t* __restrict__ B2,
                     float* __restrict__ Cq, float* __restrict__ Ck,
                     uint32_t* __restrict__ Cv, float* __restrict__ Cout,
                     int M, int N, int K)
{
    extern __shared__ __align__(16) uint32_t smu[];
    const int tid = threadIdx.x;
    const int wid = tid >> 5;
    const int lane = tid & 31;
    const int warp_m = wid >> 2;       // 0..3
    const int warp_n = wid & 3;        // 0..3
    const int by = blockIdx.y;
    int bxm = blockIdx.x, mid = 0;
    const uint32_t* Bm;
    if (MODE == 1) {
        mid = bxm >> 4;
        bxm &= 15;
        Bm = (mid == 0) ? B0 : (mid == 1) ? B1 : B2;
    } else {
        Bm = B0;
    }
    const int m0 = by * 128, n0 = bxm * 128;
    const uint32_t sbase = smem_u32(smu);
    const int fr = lane >> 2, fc = lane & 3;
    const int t3 = lane >> 3, rr = lane & 7;

    // ldmatrix per-thread row/col offsets
    const int a_row = warp_m * 32 + (t3 & 1) * 8 + rr;   // + mt*16
    const int a_col = (t3 >> 1) * 4;                      // + kb
    const int b_row = warp_n * 32 + (t3 >> 1) * 8 + rr;  // + 16 for second pair
    const int b_col = (t3 & 1) * 4;                       // + kb

    // loaders: 4 threads per row (each 2 uint4), 128 rows per tile
    const int l_r = tid >> 2, l_kq = tid & 3;
    const uint32_t* aG0 = A + (size_t)(m0 + l_r) * K + l_kq * 4;
    const uint32_t* bG0 = Bm + (size_t)(n0 + l_r) * K + l_kq * 4;
    const uint32_t aS0 = sbase + (uint32_t)(l_r * ASTRIDE + l_kq * 4) * 4;
    const uint32_t bS0 = sbase + (uint32_t)(A_FLOATS + l_r * ASTRIDE + l_kq * 4) * 4;

#define LOAD_TILE(kt, buf) do {                                               \
    const uint32_t off = (uint32_t)(buf) * (BUF_FLOATS * 4);                  \
    CP_ASYNC16(aS0 + off,      aG0 + (size_t)(kt) * 32);                      \
    CP_ASYNC16(aS0 + off + 64, aG0 + (size_t)(kt) * 32 + 16);                 \
    CP_ASYNC16(bS0 + off,      bG0 + (size_t)(kt) * 32);                      \
    CP_ASYNC16(bS0 + off + 64, bG0 + (size_t)(kt) * 32 + 16);                 \
    CP_COMMIT();                                                              \
} while (0)

    float acc[2][4][4];
#pragma unroll
    for (int mt = 0; mt < 2; mt++)
#pragma unroll
        for (int nt = 0; nt < 4; nt++)
#pragma unroll
            for (int r = 0; r < 4; r++) acc[mt][nt][r] = 0.f;

    const int KT = K / 32;
    LOAD_TILE(0, 0);

    for (int kt = 0; kt < KT; kt++) {
        const int buf = kt & 1;
        if (kt + 1 < KT) {
            LOAD_TILE(kt + 1, (kt + 1) & 1);
            CP_WAIT(1);
        } else {
            CP_WAIT(0);
        }
        __syncthreads();

        const uint32_t sA = sbase + buf * (BUF_FLOATS * 4);
        const uint32_t sB = sA + A_FLOATS * 4;

#pragma unroll
        for (int s = 0; s < 4; s++) {
            const int kb = s * 8;
            uint32_t af[2][4], bf[4][2];
            LDSM_X4(af[0][0], af[0][1], af[0][2], af[0][3],
                    sA + (uint32_t)(a_row * ASTRIDE + kb + a_col) * 4);
            LDSM_X4(af[1][0], af[1][1], af[1][2], af[1][3],
                    sA + (uint32_t)((a_row + 16) * ASTRIDE + kb + a_col) * 4);
            LDSM_X4(bf[0][0], bf[0][1], bf[1][0], bf[1][1],
                    sB + (uint32_t)(b_row * ASTRIDE + kb + b_col) * 4);
            LDSM_X4(bf[2][0], bf[2][1], bf[3][0], bf[3][1],
                    sB + (uint32_t)((b_row + 16) * ASTRIDE + kb + b_col) * 4);
#pragma unroll
            for (int mt = 0; mt < 2; mt++)
#pragma unroll
                for (int nt = 0; nt < 4; nt++)
                    MMA_TF32(acc[mt][nt], af[mt][0], af[mt][1], af[mt][2], af[mt][3],
                             bf[nt][0], bf[nt][1]);
        }
        __syncthreads();
    }

    // epilogue
#pragma unroll
    for (int mt = 0; mt < 2; mt++) {
#pragma unroll
        for (int nt = 0; nt < 4; nt++) {
            const int r0 = m0 + warp_m * 32 + mt * 16 + fr;
            const int nloc = warp_n * 32 + nt * 8 + fc * 2;
            float2 v0 = make_float2(acc[mt][nt][0], acc[mt][nt][1]);
            float2 v1 = make_float2(acc[mt][nt][2], acc[mt][nt][3]);
            if (MODE == 1) {
                const int b0_ = r0 >> 11, l0 = r0 & 2047;
                const int b1_ = (r0 + 8) >> 11, l1 = (r0 + 8) & 2047;
                if (mid == 2) {
                    // transposed V: [b][h][d][l], tf32 bits
                    const size_t vb0 = ((size_t)(b0_ * HH + bxm) * DH + nloc) * LL;
                    const size_t vb1 = ((size_t)(b1_ * HH + bxm) * DH + nloc) * LL;
                    Cv[vb0 + l0]      = f2tf32(v0.x);
                    Cv[vb0 + LL + l0] = f2tf32(v0.y);
                    Cv[vb1 + l1]      = f2tf32(v1.x);
                    Cv[vb1 + LL + l1] = f2tf32(v1.y);
                } else {
                    float* Ct = (mid == 0) ? Cq : Ck;
                    const size_t o0 = (((size_t)(b0_ * HH + bxm)) * LL + l0) * DH + nloc;
                    const size_t o1 = (((size_t)(b1_ * HH + bxm)) * LL + l1) * DH + nloc;
                    *(float2*)(Ct + o0) = v0;
                    *(float2*)(Ct + o1) = v1;
                }
            } else {
                *(float2*)(Cout + (size_t)r0 * N + n0 + nloc) = v0;
                *(float2*)(Cout + (size_t)(r0 + 8) * N + n0 + nloc) = v1;
            }
        }
    }
#undef LOAD_TILE
}

// ---------------- RoPE + L2-normalize; writes tf32 bits in place ----------------
__global__ __launch_bounds__(256)
void rope_norm_kernel(float* __restrict__ t)
{
    const int gw = (blockIdx.x * 256 + threadIdx.x) >> 5;
    const int lane = threadIdx.x & 31;
    const int pos = gw & (LL - 1);
    float* row = t + (size_t)gw * DH;

    const float invf0 = g_invf[lane];
    const float invf1 = g_invf[lane + 32];
    const float pf = (float)pos;
    float s0, c0, s1, c1;
    sincosf(pf * invf0, &s0, &c0);
    sincosf(pf * invf1, &s1, &c1);

    float2 x = ((const float2*)row)[lane];
    float2 y = ((const float2*)row)[lane + 32];
    const float r0 = x.x * c0 - x.y * s0;
    const float r1 = x.y * c0 + x.x * s0;
    const float r2 = y.x * c1 - y.y * s1;
    const float r3 = y.y * c1 + y.x * s1;

    float ss = r0 * r0 + r1 * r1 + r2 * r2 + r3 * r3;
#pragma unroll
    for (int off = 16; off > 0; off >>= 1)
        ss += __shfl_xor_sync(0xffffffffu, ss, off);
    const float inv = 1.0f / (sqrtf(ss) + 1e-6f);

    uint32_t* rowu = (uint32_t*)row;
    ((uint2*)rowu)[lane]      = make_uint2(f2tf32(r0 * inv), f2tf32(r1 * inv));
    ((uint2*)rowu)[lane + 32] = make_uint2(f2tf32(r2 * inv), f2tf32(r3 * inv));
}

// ============================================================================
// tensor-core causal flash attention on tf32 bits, ldmatrix feeds
// k_s: K[kpos][d] stride 132 (also Q staging); v_s: Vt[d][kpos] stride 68;
// p_s: P[q][kpos] stride 68.
// ============================================================================
#define AKS 132
#define AVS 68
#define APS 68
#define AV_OFF (64 * AKS)                  // 8448
#define AP_OFF (AV_OFF + 128 * AVS)        // 17152
#define ATTN2_U32 (AP_OFF + 64 * APS)      // 21504
#define ATTN2_BYTES (ATTN2_U32 * 4)        // 86016

__global__ __launch_bounds__(128, 2)
void attn_mma_kernel(const float* __restrict__ scale_ptr)
{
    extern __shared__ __align__(16) uint32_t smu[];
    uint32_t* k_u = smu;
    uint32_t* v_u = smu + AV_OFF;
    uint32_t* p_u = smu + AP_OFF;

    const int qt = (int)gridDim.x - 1 - (int)blockIdx.x;   // heavy tiles first
    const int h = blockIdx.y, b = blockIdx.z;
    const int tid = threadIdx.x;
    const int wid = tid >> 5, lane = tid & 31;
    const int fr = lane >> 2, fc = lane & 3;
    const int t3 = lane >> 3, rr = lane & 7;
    const float sc2 = (*scale_ptr) * 1.4426950408889634f;

    const size_t head_off = (size_t)(b * HH + h) * LL * DH;
    const uint32_t* qptr = (const uint32_t*)g_q + head_off;
    const uint32_t* kptr = (const uint32_t*)g_k + head_off;
    const uint32_t* vtptr = g_v + head_off;          // [d][l] layout
    const int q0 = qt * 64;

    const uint32_t sK = smem_u32(smu);
    const uint32_t sV = sK + AV_OFF * 4;
    const uint32_t sP = sK + AP_OFF * 4;

    const int lr = tid >> 1, lh = tid & 1;           // K/Q loader slot
    const int vrow = tid >> 1, vhalf = tid & 1;      // V loader slot

    // ---- stage Q bits into k_s, preload A-frags via ldmatrix ----
    {
        const uint32_t* src = qptr + (size_t)(q0 + lr) * DH + lh * 64;
        uint32_t* dst = k_u + lr * AKS + lh * 64;
#pragma unroll
        for (int j = 0; j < 16; j++)
            *(uint4*)(dst + j * 4) = *(const uint4*)(src + j * 4);
    }
    __syncthreads();
    uint32_t qa[16][4];
    {
        const uint32_t qbase = sK +
            (uint32_t)((wid * 16 + (t3 & 1) * 8 + rr) * AKS + (t3 >> 1) * 4) * 4;
#pragma unroll
        for (int s = 0; s < 16; s++)
            LDSM_X4(qa[s][0], qa[s][1], qa[s][2], qa[s][3], qbase + (uint32_t)(s * 8) * 4);
    }

    float oacc[16][4];
#pragma unroll
    for (int nf = 0; nf < 16; nf++)
#pragma unroll
        for (int r = 0; r < 4; r++) oacc[nf][r] = 0.f;
    float m_[2] = {-1e30f, -1e30f};
    float l_[2] = {0.f, 0.f};

    const int row0 = q0 + wid * 16 + fr;

    // ldmatrix per-thread bases (row/col offsets inside tiles)
    const int kb_row = (t3 >> 1) * 8 + rr;   // + 16*jj  (K B-frags)
    const int kb_col = (t3 & 1) * 4;         // + 8*s
    const int vb_row = (t3 >> 1) * 8 + rr;   // + 16*nfp (V B-frags)
    const int vb_col = (t3 & 1) * 4;         // + 8*s2
    const int pa_row = wid * 16 + (t3 & 1) * 8 + rr;
    const int pa_col = (t3 >> 1) * 4;        // + 8*s2

    for (int kt = 0; kt <= qt; kt++) {
        const int k0 = kt * 64;
        __syncthreads();
        {
            // K: [kpos][d] rows, coalesced
            const uint32_t* ksrc = kptr + (size_t)(k0 + lr) * DH + lh * 64;
            uint32_t* kdst = k_u + lr * AKS + lh * 64;
#pragma unroll
            for (int j = 0; j < 16; j++)
                *(uint4*)(kdst + j * 4) = *(const uint4*)(ksrc + j * 4);
            // V: gmem [d][l] rows -> smem [d][kpos] rows
#pragma unroll
            for (int rp = 0; rp < 2; rp++) {
                const int d = vrow + rp * 64;
                const uint32_t* vsrc = vtptr + (size_t)d * LL + k0 + vhalf * 32;
                uint32_t* vdst = v_u + d * AVS + vhalf * 32;
#pragma unroll
                for (int j = 0; j < 8; j++)
                    *(uint4*)(vdst + j * 4) = *(const uint4*)(vsrc + j * 4);
            }
        }
        __syncthreads();

        // ---- S = Q K^T ----
        float sacc[8][4];
#pragma unroll
        for (int j = 0; j < 8; j++)
#pragma unroll
            for (int r = 0; r < 4; r++) sacc[j][r] = 0.f;

#pragma unroll
        for (int s = 0; s < 16; s++) {
#pragma unroll
            for (int jj = 0; jj < 4; jj++) {
                uint32_t b0a, b1a, b0b, b1b;
                LDSM_X4(b0a, b1a, b0b, b1b,
                        sK + (uint32_t)((jj * 16 + kb_row) * AKS + s * 8 + kb_col) * 4);
                MMA_TF32(sacc[2 * jj],     qa[s][0], qa[s][1], qa[s][2], qa[s][3], b0a, b1a);
                MMA_TF32(sacc[2 * jj + 1], qa[s][0], qa[s][1], qa[s][2], qa[s][3], b0b, b1b);
            }
        }

        // ---- mask (diagonal tile only) ----
        if (kt == qt) {
#pragma unroll
            for (int j = 0; j < 8; j++) {
                const int c0 = k0 + 8 * j + 2 * fc;
                if (c0 > row0)     sacc[j][0] = -1e30f;
                if (c0 + 1 > row0) sacc[j][1] = -1e30f;
                if (c0 > row0 + 8)     sacc[j][2] = -1e30f;
                if (c0 + 1 > row0 + 8) sacc[j][3] = -1e30f;
            }
        }

        // ---- online softmax ----
#pragma unroll
        for (int r2 = 0; r2 < 2; r2++) {
            float rmax = -1e30f;
#pragma unroll
            for (int j = 0; j < 8; j++)
                rmax = fmaxf(rmax, fmaxf(sacc[j][2 * r2], sacc[j][2 * r2 + 1]));
            rmax = fmaxf(rmax, __shfl_xor_sync(0xffffffffu, rmax, 1));
            rmax = fmaxf(rmax, __shfl_xor_sync(0xffffffffu, rmax, 2));
            const float mn = fmaxf(m_[r2], rmax);
            const float fs = fast_exp2(sc2 * (m_[r2] - mn));
            const float base = sc2 * mn;
            float rs = 0.f;
            uint32_t* prow = p_u + (wid * 16 + fr + 8 * r2) * APS + 2 * fc;
#pragma unroll
            for (int j = 0; j < 8; j++) {
                float p0 = fast_exp2(__fmaf_rn(sc2, sacc[j][2 * r2], -base));
                float p1 = fast_exp2(__fmaf_rn(sc2, sacc[j][2 * r2 + 1], -base));
                rs += p0 + p1;
                prow[8 * j]     = f2tf32(p0);
                prow[8 * j + 1] = f2tf32(p1);
            }
            rs += __shfl_xor_sync(0xffffffffu, rs, 1);
            rs += __shfl_xor_sync(0xffffffffu, rs, 2);
            l_[r2] = l_[r2] * fs + rs;
            m_[r2] = mn;
#pragma unroll
            for (int nf = 0; nf < 16; nf++) {
                oacc[nf][2 * r2]     *= fs;
                oacc[nf][2 * r2 + 1] *= fs;
            }
        }
        __syncwarp();

        // ---- O += P V ----
#pragma unroll
        for (int s2 = 0; s2 < 8; s2++) {
            uint32_t a0, a1, a2, a3;
            LDSM_X4(a0, a1, a2, a3,
                    sP + (uint32_t)(pa_row * APS + s2 * 8 + pa_col) * 4);
#pragma unroll
            for (int nfp = 0; nfp < 8; nfp++) {
                uint32_t b0a, b1a, b0b, b1b;
                LDSM_X4(b0a, b1a, b0b, b1b,
                        sV + (uint32_t)((nfp * 16 + vb_row) * AVS + s2 * 8 + vb_col) * 4);
                MMA_TF32(oacc[2 * nfp],     a0, a1, a2, a3, b0a, b1a);
                MMA_TF32(oacc[2 * nfp + 1], a0, a1, a2, a3, b0b, b1b);
            }
        }
        __syncwarp();
    }

    // ---- epilogue: normalize + write tf32 bits [b][l][h*128+d] ----
    const float inv0 = 1.f / l_[0];
    const float inv1 = 1.f / l_[1];
    uint32_t* d0p = g_attn + ((size_t)(b * LL + row0)) * DD + h * DH + 2 * fc;
    uint32_t* d1p = g_attn + ((size_t)(b * LL + row0 + 8)) * DD + h * DH + 2 * fc;
#pragma unroll
    for (int nf = 0; nf < 16; nf++) {
        *(uint2*)(d0p + 8 * nf) = make_uint2(f2tf32(oacc[nf][0] * inv0),
                                             f2tf32(oacc[nf][1] * inv0));
        *(uint2*)(d1p + 8 * nf) = make_uint2(f2tf32(oacc[nf][2] * inv1),
                                             f2tf32(oacc[nf][3] * inv1));
    }
}

// ---------------- launch ----------------
extern "C" void kernel_launch(void* const* d_in, const int* in_sizes, int n_in,
                              void* d_out, int out_size)
{
    const float* x     = (const float*)d_in[0];
    const float* Wq    = (const float*)d_in[1];
    const float* Wk    = (const float*)d_in[2];
    const float* Wv    = (const float*)d_in[3];
    const float* Wout  = (const float*)d_in[4];
    const float* scale = (const float*)d_in[5];
    float* out = (float*)d_out;

    float *qp, *kp;
    uint32_t *vp, *ap, *xc, *wqc, *wkc, *wvc, *woc;
    cudaGetSymbolAddress((void**)&qp,  g_q);
    cudaGetSymbolAddress((void**)&kp,  g_k);
    cudaGetSymbolAddress((void**)&vp,  g_v);
    cudaGetSymbolAddress((void**)&ap,  g_attn);
    cudaGetSymbolAddress((void**)&xc,  g_xc);
    cudaGetSymbolAddress((void**)&wqc, g_wqc);
    cudaGetSymbolAddress((void**)&wkc, g_wkc);
    cudaGetSymbolAddress((void**)&wvc, g_wvc);
    cudaGetSymbolAddress((void**)&woc, g_woc);

    build_invf_kernel<<<1, 64>>>();

    const int M = BB * LL;           // 4096
    const int XN4 = (M * DD) / 4;
    cvt_kernel<<<XN4 / 256, 256>>>(x, xc, XN4);
    dim3 tgrid(DD / 32, DD / 32);
    cvt_t_kernel<<<tgrid, 256>>>(Wq, wqc);
    cvt_t_kernel<<<tgrid, 256>>>(Wk, wkc);
    cvt_t_kernel<<<tgrid, 256>>>(Wv, wvc);
    cvt_t_kernel<<<tgrid, 256>>>(Wout, woc);

    cudaFuncSetAttribute(mma_gemm_kernel<0>, cudaFuncAttributeMaxDynamicSharedMemorySize,
                         GEMM_SMEM_BYTES);
    cudaFuncSetAttribute(mma_gemm_kernel<1>, cudaFuncAttributeMaxDynamicSharedMemorySize,
                         GEMM_SMEM_BYTES);
    cudaFuncSetAttribute(attn_mma_kernel, cudaFuncAttributeMaxDynamicSharedMemorySize,
                         ATTN2_BYTES);

    // fused QKV: grid.x = 48 (16 n-blocks x 3 matrices)
    mma_gemm_kernel<1><<<dim3(48, M / 128), 512, GEMM_SMEM_BYTES>>>(
        xc, wqc, wkc, wvc, qp, kp, vp, nullptr, M, DD, DD);

    const int rope_blocks = (BB * HH * LL) / 8;
    rope_norm_kernel<<<rope_blocks, 256>>>(qp);
    rope_norm_kernel<<<rope_blocks, 256>>>(kp);

    attn_mma_kernel<<<dim3(LL / 64, HH, BB), 128, ATTN2_BYTES>>>(scale);

    mma_gemm_kernel<0><<<dim3(16, M / 128), 512, GEMM_SMEM_BYTES>>>(
        ap, woc, nullptr, nullptr, nullptr, nullptr, nullptr, out, M, DD, DD);
}

// round 12
// speedup vs baseline: 1.3558x; 1.3558x over previous
#include <cuda_runtime.h>
#include <cstdint>
#include <cmath>

#define BB 2
#define LL 2048
#define DD 2048
#define HH 16
#define DH 128

// ---------------- scratch ----------------
__device__ float    g_q[(size_t)BB * HH * LL * DH];     // fp32 after GEMM, tf32 bits after rope
__device__ float    g_k[(size_t)BB * HH * LL * DH];
__device__ uint32_t g_v[(size_t)BB * HH * LL * DH];     // tf32 bits, TRANSPOSED: [b][h][d][l]
__device__ uint32_t g_attn[(size_t)BB * LL * DD];       // tf32 bits
__device__ uint32_t g_xc[(size_t)BB * LL * DD];         // x as tf32 bits
__device__ uint32_t g_wqc[(size_t)DD * DD];             // W^T as tf32 bits  [n][k]
__device__ uint32_t g_wkc[(size_t)DD * DD];
__device__ uint32_t g_wvc[(size_t)DD * DD];
__device__ uint32_t g_woc[(size_t)DD * DD];
__device__ float    g_invf[64];

__global__ void build_invf_kernel() {
    int i = threadIdx.x;
    if (i < 64) {
        double e = (double)(2 * i) / 128.0;
        g_invf[i] = (float)pow(500000.0, -e);
    }
}

__device__ __forceinline__ uint32_t smem_u32(const void* p) {
    uint32_t a;
    asm("{ .reg .u64 t; cvta.to.shared.u64 t, %1; cvt.u32.u64 %0, t; }"
        : "=r"(a) : "l"(p));
    return a;
}

__device__ __forceinline__ uint32_t f2tf32(float f) {
    uint32_t u;
    asm("cvt.rna.tf32.f32 %0, %1;" : "=r"(u) : "f"(f));
    return u;
}

__device__ __forceinline__ float fast_exp2(float x) {
    float r;
    asm("ex2.approx.ftz.f32 %0, %1;" : "=f"(r) : "f"(x));
    return r;
}

#define MMA_TF32(acc, a0, a1, a2, a3, b0, b1)                                 \
    asm volatile(                                                             \
        "mma.sync.aligned.m16n8k8.row.col.f32.tf32.tf32.f32 "                 \
        "{%0,%1,%2,%3}, {%4,%5,%6,%7}, {%8,%9}, {%0,%1,%2,%3};"               \
        : "+f"((acc)[0]), "+f"((acc)[1]), "+f"((acc)[2]), "+f"((acc)[3])      \
        : "r"(a0), "r"(a1), "r"(a2), "r"(a3), "r"(b0), "r"(b1))

#define LDSM_X4(r0, r1, r2, r3, addr)                                         \
    asm volatile("ldmatrix.sync.aligned.m8n8.x4.shared.b16 {%0,%1,%2,%3}, [%4];" \
                 : "=r"(r0), "=r"(r1), "=r"(r2), "=r"(r3) : "r"(addr))

#define CP_ASYNC16(saddr, gptr)                                               \
    asm volatile("cp.async.cg.shared.global [%0], [%1], 16;"                  \
                 :: "r"(saddr), "l"(gptr))
#define CP_COMMIT() asm volatile("cp.async.commit_group;")
#define CP_WAIT(n)  asm volatile("cp.async.wait_group %0;" :: "n"(n))

// ---------------- fp32 -> tf32-bits converters ----------------
__global__ __launch_bounds__(256)
void cvt_kernel(const float* __restrict__ s, uint32_t* __restrict__ d, int n4)
{
    int i = blockIdx.x * 256 + threadIdx.x;
    if (i < n4) {
        float4 v = ((const float4*)s)[i];
        ((uint4*)d)[i] = make_uint4(f2tf32(v.x), f2tf32(v.y), f2tf32(v.z), f2tf32(v.w));
    }
}

// transpose + convert: W [k][n] fp32 -> Wt [n][k] tf32 bits
__global__ __launch_bounds__(256)
void cvt_t_kernel(const float* __restrict__ s, uint32_t* __restrict__ d)
{
    __shared__ uint32_t tile[32][33];
    const int tx = threadIdx.x & 31, ty = threadIdx.x >> 5;
    const int c0 = blockIdx.x * 32, r0 = blockIdx.y * 32;
#pragma unroll
    for (int i = 0; i < 4; i++)
        tile[ty + i * 8][tx] = f2tf32(s[(size_t)(r0 + ty + i * 8) * DD + c0 + tx]);
    __syncthreads();
#pragma unroll
    for (int i = 0; i < 4; i++)
        d[(size_t)(c0 + ty + i * 8) * DD + r0 + tx] = tile[tx][ty + i * 8];
}

// ============================================================================
// tf32 mma GEMM, ldmatrix feeds: C[M,N] = A[M,K] @ Bt^T  (Bt is [n][k])
// CTA 128x128, 8 warps (2m x 4n), warp 64x32.  (reverted to R9 config)
// ============================================================================
#define ASTRIDE 36
#define A_FLOATS (128 * ASTRIDE)          // 4608
#define B_FLOATS (128 * ASTRIDE)          // 4608
#define BUF_FLOATS (A_FLOATS + B_FLOATS)  // 9216
#define GEMM_SMEM_BYTES (2 * BUF_FLOATS * 4)  // 73728

template <int MODE>
__global__ __launch_bounds__(256, 2)
void mma_gemm_kernel(const uint32_t* __restrict__ A,
                     const uint32_t* __restrict__ B0,
                     const uint32_t* __restrict__ B1,
                     const uint32_t* __restrict__ B2,
                     float* __restrict__ Cq, float* __restrict__ Ck,
                     uint32_t* __restrict__ Cv, float* __restrict__ Cout,
                     int M, int N, int K)
{
    extern __shared__ __align__(16) uint32_t smu[];
    const int tid = threadIdx.x;
    const int wid = tid >> 5;
    const int lane = tid & 31;
    const int warp_m = wid >> 2;       // 0..1
    const int warp_n = wid & 3;        // 0..3
    const int by = blockIdx.y;
    int bxm = blockIdx.x, mid = 0;
    const uint32_t* Bm;
    if (MODE == 1) {
        mid = bxm >> 4;
        bxm &= 15;
        Bm = (mid == 0) ? B0 : (mid == 1) ? B1 : B2;
    } else {
        Bm = B0;
    }
    const int m0 = by * 128, n0 = bxm * 128;
    const uint32_t sbase = smem_u32(smu);
    const int fr = lane >> 2, fc = lane & 3;
    const int t3 = lane >> 3, rr = lane & 7;

    // ldmatrix per-thread row/col offsets
    const int a_row = warp_m * 64 + (t3 & 1) * 8 + rr;   // + mt*16
    const int a_col = (t3 >> 1) * 4;                      // + kb
    const int b_row = warp_n * 32 + (t3 >> 1) * 8 + rr;  // + 16 for second pair
    const int b_col = (t3 & 1) * 4;                       // + kb

    // loaders: 8 threads per row, 32 rows per pass, 4 passes
    const int l_r = tid >> 3, l_kq = tid & 7;
    const uint32_t* aG0 = A + (size_t)(m0 + l_r) * K + l_kq * 4;
    const uint32_t* bG0 = Bm + (size_t)(n0 + l_r) * K + l_kq * 4;
    const uint32_t aS0 = sbase + (uint32_t)(l_r * ASTRIDE + l_kq * 4) * 4;
    const uint32_t bS0 = sbase + (uint32_t)(A_FLOATS + l_r * ASTRIDE + l_kq * 4) * 4;

#define LOAD_TILE(kt, buf) do {                                               \
    const uint32_t off = (uint32_t)(buf) * (BUF_FLOATS * 4);                  \
    _Pragma("unroll")                                                         \
    for (int i = 0; i < 4; i++)                                               \
        CP_ASYNC16(aS0 + off + (uint32_t)(i * 32 * ASTRIDE) * 4,              \
                   aG0 + (size_t)(i * 32) * K + (kt) * 32);                   \
    _Pragma("unroll")                                                         \
    for (int i = 0; i < 4; i++)                                               \
        CP_ASYNC16(bS0 + off + (uint32_t)(i * 32 * ASTRIDE) * 4,              \
                   bG0 + (size_t)(i * 32) * K + (kt) * 32);                   \
    CP_COMMIT();                                                              \
} while (0)

    float acc[4][4][4];
#pragma unroll
    for (int mt = 0; mt < 4; mt++)
#pragma unroll
        for (int nt = 0; nt < 4; nt++)
#pragma unroll
            for (int r = 0; r < 4; r++) acc[mt][nt][r] = 0.f;

    const int KT = K / 32;
    LOAD_TILE(0, 0);

    for (int kt = 0; kt < KT; kt++) {
        const int buf = kt & 1;
        if (kt + 1 < KT) {
            LOAD_TILE(kt + 1, (kt + 1) & 1);
            CP_WAIT(1);
        } else {
            CP_WAIT(0);
        }
        __syncthreads();

        const uint32_t sA = sbase + buf * (BUF_FLOATS * 4);
        const uint32_t sB = sA + A_FLOATS * 4;

#pragma unroll
        for (int s = 0; s < 4; s++) {
            const int kb = s * 8;
            uint32_t af[4][4], bf[4][2];
#pragma unroll
            for (int mt = 0; mt < 4; mt++)
                LDSM_X4(af[mt][0], af[mt][1], af[mt][2], af[mt][3],
                        sA + (uint32_t)((a_row + mt * 16) * ASTRIDE + kb + a_col) * 4);
            LDSM_X4(bf[0][0], bf[0][1], bf[1][0], bf[1][1],
                    sB + (uint32_t)(b_row * ASTRIDE + kb + b_col) * 4);
            LDSM_X4(bf[2][0], bf[2][1], bf[3][0], bf[3][1],
                    sB + (uint32_t)((b_row + 16) * ASTRIDE + kb + b_col) * 4);
#pragma unroll
            for (int mt = 0; mt < 4; mt++)
#pragma unroll
                for (int nt = 0; nt < 4; nt++)
                    MMA_TF32(acc[mt][nt], af[mt][0], af[mt][1], af[mt][2], af[mt][3],
                             bf[nt][0], bf[nt][1]);
        }
        __syncthreads();
    }

    // epilogue
#pragma unroll
    for (int mt = 0; mt < 4; mt++) {
#pragma unroll
        for (int nt = 0; nt < 4; nt++) {
            const int r0 = m0 + warp_m * 64 + mt * 16 + fr;
            const int nloc = warp_n * 32 + nt * 8 + fc * 2;
            float2 v0 = make_float2(acc[mt][nt][0], acc[mt][nt][1]);
            float2 v1 = make_float2(acc[mt][nt][2], acc[mt][nt][3]);
            if (MODE == 1) {
                const int b0_ = r0 >> 11, l0 = r0 & 2047;
                const int b1_ = (r0 + 8) >> 11, l1 = (r0 + 8) & 2047;
                if (mid == 2) {
                    // transposed V: [b][h][d][l], tf32 bits
                    const size_t vb0 = ((size_t)(b0_ * HH + bxm) * DH + nloc) * LL;
                    const size_t vb1 = ((size_t)(b1_ * HH + bxm) * DH + nloc) * LL;
                    Cv[vb0 + l0]      = f2tf32(v0.x);
                    Cv[vb0 + LL + l0] = f2tf32(v0.y);
                    Cv[vb1 + l1]      = f2tf32(v1.x);
                    Cv[vb1 + LL + l1] = f2tf32(v1.y);
                } else {
                    float* Ct = (mid == 0) ? Cq : Ck;
                    const size_t o0 = (((size_t)(b0_ * HH + bxm)) * LL + l0) * DH + nloc;
                    const size_t o1 = (((size_t)(b1_ * HH + bxm)) * LL + l1) * DH + nloc;
                    *(float2*)(Ct + o0) = v0;
                    *(float2*)(Ct + o1) = v1;
                }
            } else {
                *(float2*)(Cout + (size_t)r0 * N + n0 + nloc) = v0;
                *(float2*)(Cout + (size_t)(r0 + 8) * N + n0 + nloc) = v1;
            }
        }
    }
#undef LOAD_TILE
}

// ---------------- RoPE + L2-normalize; writes tf32 bits in place ----------------
__global__ __launch_bounds__(256)
void rope_norm_kernel(float* __restrict__ t)
{
    const int gw = (blockIdx.x * 256 + threadIdx.x) >> 5;
    const int lane = threadIdx.x & 31;
    const int pos = gw & (LL - 1);
    float* row = t + (size_t)gw * DH;

    const float invf0 = g_invf[lane];
    const float invf1 = g_invf[lane + 32];
    const float pf = (float)pos;
    float s0, c0, s1, c1;
    sincosf(pf * invf0, &s0, &c0);
    sincosf(pf * invf1, &s1, &c1);

    float2 x = ((const float2*)row)[lane];
    float2 y = ((const float2*)row)[lane + 32];
    const float r0 = x.x * c0 - x.y * s0;
    const float r1 = x.y * c0 + x.x * s0;
    const float r2 = y.x * c1 - y.y * s1;
    const float r3 = y.y * c1 + y.x * s1;

    float ss = r0 * r0 + r1 * r1 + r2 * r2 + r3 * r3;
#pragma unroll
    for (int off = 16; off > 0; off >>= 1)
        ss += __shfl_xor_sync(0xffffffffu, ss, off);
    const float inv = 1.0f / (sqrtf(ss) + 1e-6f);

    uint32_t* rowu = (uint32_t*)row;
    ((uint2*)rowu)[lane]      = make_uint2(f2tf32(r0 * inv), f2tf32(r1 * inv));
    ((uint2*)rowu)[lane + 32] = make_uint2(f2tf32(r2 * inv), f2tf32(r3 * inv));
}

// ============================================================================
// tensor-core causal flash attention, q-tile 128, 256 threads (8 warps x 16 q)
// k_s: K[kpos][d] stride 132 (also Q staging, 2 passes); v_s: Vt[d][kpos] 68;
// p_s: P[q][kpos] 68 (128 rows).
// ============================================================================
#define AKS 132
#define AVS 68
#define APS 68
#define AV_OFF (64 * AKS)                  // 8448
#define AP_OFF (AV_OFF + 128 * AVS)        // 17152
#define ATTN2_U32 (AP_OFF + 128 * APS)     // 25856
#define ATTN2_BYTES (ATTN2_U32 * 4)        // 103424

__global__ __launch_bounds__(256, 1)
void attn_mma_kernel(const float* __restrict__ scale_ptr)
{
    extern __shared__ __align__(16) uint32_t smu[];
    uint32_t* k_u = smu;
    uint32_t* v_u = smu + AV_OFF;
    uint32_t* p_u = smu + AP_OFF;

    const int qt = (int)gridDim.x - 1 - (int)blockIdx.x;   // heavy tiles first
    const int h = blockIdx.y, b = blockIdx.z;
    const int tid = threadIdx.x;
    const int wid = tid >> 5, lane = tid & 31;
    const int fr = lane >> 2, fc = lane & 3;
    const int t3 = lane >> 3, rr = lane & 7;
    const float sc2 = (*scale_ptr) * 1.4426950408889634f;

    const size_t head_off = (size_t)(b * HH + h) * LL * DH;
    const uint32_t* qptr = (const uint32_t*)g_q + head_off;
    const uint32_t* kptr = (const uint32_t*)g_k + head_off;
    const uint32_t* vtptr = g_v + head_off;          // [d][l] layout
    const int q0 = qt * 128;

    const uint32_t sK = smem_u32(smu);
    const uint32_t sV = sK + AV_OFF * 4;
    const uint32_t sP = sK + AP_OFF * 4;

    const int lr = tid >> 2, lq = tid & 3;           // K/Q loader: 64 rows, 4 thr/row
    const int vr = tid >> 1, vh = tid & 1;           // V loader: 128 rows, 2 thr/row

    // ---- stage Q bits (two 64-row passes through k_s), preload A-frags ----
    uint32_t qa[16][4];
    const uint32_t qbase = sK +
        (uint32_t)(((wid & 3) * 16 + (t3 & 1) * 8 + rr) * AKS + (t3 >> 1) * 4) * 4;
    for (int pass = 0; pass < 2; pass++) {
        const uint32_t* src = qptr + (size_t)(q0 + pass * 64 + lr) * DH + lq * 32;
        uint32_t* dst = k_u + lr * AKS + lq * 32;
#pragma unroll
        for (int j = 0; j < 8; j++)
            *(uint4*)(dst + j * 4) = *(const uint4*)(src + j * 4);
        __syncthreads();
        if ((wid >> 2) == pass) {
#pragma unroll
            for (int s = 0; s < 16; s++)
                LDSM_X4(qa[s][0], qa[s][1], qa[s][2], qa[s][3],
                        qbase + (uint32_t)(s * 8) * 4);
        }
        __syncthreads();
    }

    float oacc[16][4];
#pragma unroll
    for (int nf = 0; nf < 16; nf++)
#pragma unroll
        for (int r = 0; r < 4; r++) oacc[nf][r] = 0.f;
    float m_[2] = {-1e30f, -1e30f};
    float l_[2] = {0.f, 0.f};

    const int row0 = q0 + wid * 16 + fr;

    // ldmatrix per-thread bases
    const int kb_row = (t3 >> 1) * 8 + rr;   // + 16*jj  (K B-frags)
    const int kb_col = (t3 & 1) * 4;         // + 8*s
    const int vb_row = (t3 >> 1) * 8 + rr;   // + 16*nfp (V B-frags)
    const int vb_col = (t3 & 1) * 4;         // + 8*s2
    const int pa_row = wid * 16 + (t3 & 1) * 8 + rr;
    const int pa_col = (t3 >> 1) * 4;        // + 8*s2

    const int KTend = 2 * qt + 1;
    for (int kt = 0; kt <= KTend; kt++) {
        const int k0 = kt * 64;
        __syncthreads();
        {
            // K: [kpos][d] rows, coalesced (64 rows x 128)
            const uint32_t* ksrc = kptr + (size_t)(k0 + lr) * DH + lq * 32;
            uint32_t* kdst = k_u + lr * AKS + lq * 32;
#pragma unroll
            for (int j = 0; j < 8; j++)
                *(uint4*)(kdst + j * 4) = *(const uint4*)(ksrc + j * 4);
            // V: gmem [d][l] rows -> smem [d][kpos] rows (128 rows x 64)
            const uint32_t* vsrc = vtptr + (size_t)vr * LL + k0 + vh * 32;
            uint32_t* vdst = v_u + vr * AVS + vh * 32;
#pragma unroll
            for (int j = 0; j < 8; j++)
                *(uint4*)(vdst + j * 4) = *(const uint4*)(vsrc + j * 4);
        }
        __syncthreads();

        // ---- S = Q K^T ----
        float sacc[8][4];
#pragma unroll
        for (int j = 0; j < 8; j++)
#pragma unroll
            for (int r = 0; r < 4; r++) sacc[j][r] = 0.f;

#pragma unroll
        for (int s = 0; s < 16; s++) {
#pragma unroll
            for (int jj = 0; jj < 4; jj++) {
                uint32_t b0a, b1a, b0b, b1b;
                LDSM_X4(b0a, b1a, b0b, b1b,
                        sK + (uint32_t)((jj * 16 + kb_row) * AKS + s * 8 + kb_col) * 4);
                MMA_TF32(sacc[2 * jj],     qa[s][0], qa[s][1], qa[s][2], qa[s][3], b0a, b1a);
                MMA_TF32(sacc[2 * jj + 1], qa[s][0], qa[s][1], qa[s][2], qa[s][3], b0b, b1b);
            }
        }

        // ---- mask (last two k-tiles straddle the diagonal) ----
        if (kt >= 2 * qt) {
#pragma unroll
            for (int j = 0; j < 8; j++) {
                const int c0 = k0 + 8 * j + 2 * fc;
                if (c0 > row0)     sacc[j][0] = -1e30f;
                if (c0 + 1 > row0) sacc[j][1] = -1e30f;
                if (c0 > row0 + 8)     sacc[j][2] = -1e30f;
                if (c0 + 1 > row0 + 8) sacc[j][3] = -1e30f;
            }
        }

        // ---- online softmax ----
#pragma unroll
        for (int r2 = 0; r2 < 2; r2++) {
            float rmax = -1e30f;
#pragma unroll
            for (int j = 0; j < 8; j++)
                rmax = fmaxf(rmax, fmaxf(sacc[j][2 * r2], sacc[j][2 * r2 + 1]));
            rmax = fmaxf(rmax, __shfl_xor_sync(0xffffffffu, rmax, 1));
            rmax = fmaxf(rmax, __shfl_xor_sync(0xffffffffu, rmax, 2));
            const float mn = fmaxf(m_[r2], rmax);
            const float fs = fast_exp2(sc2 * (m_[r2] - mn));
            const float base = sc2 * mn;
            float rs = 0.f;
            uint32_t* prow = p_u + (wid * 16 + fr + 8 * r2) * APS + 2 * fc;
#pragma unroll
            for (int j = 0; j < 8; j++) {
                float p0 = fast_exp2(__fmaf_rn(sc2, sacc[j][2 * r2], -base));
                float p1 = fast_exp2(__fmaf_rn(sc2, sacc[j][2 * r2 + 1], -base));
                rs += p0 + p1;
                prow[8 * j]     = f2tf32(p0);
                prow[8 * j + 1] = f2tf32(p1);
            }
            rs += __shfl_xor_sync(0xffffffffu, rs, 1);
            rs += __shfl_xor_sync(0xffffffffu, rs, 2);
            l_[r2] = l_[r2] * fs + rs;
            m_[r2] = mn;
#pragma unroll
            for (int nf = 0; nf < 16; nf++) {
                oacc[nf][2 * r2]     *= fs;
                oacc[nf][2 * r2 + 1] *= fs;
            }
        }
        __syncwarp();

        // ---- O += P V ----
#pragma unroll
        for (int s2 = 0; s2 < 8; s2++) {
            uint32_t a0, a1, a2, a3;
            LDSM_X4(a0, a1, a2, a3,
                    sP + (uint32_t)(pa_row * APS + s2 * 8 + pa_col) * 4);
#pragma unroll
            for (int nfp = 0; nfp < 8; nfp++) {
                uint32_t b0a, b1a, b0b, b1b;
                LDSM_X4(b0a, b1a, b0b, b1b,
                        sV + (uint32_t)((nfp * 16 + vb_row) * AVS + s2 * 8 + vb_col) * 4);
                MMA_TF32(oacc[2 * nfp],     a0, a1, a2, a3, b0a, b1a);
                MMA_TF32(oacc[2 * nfp + 1], a0, a1, a2, a3, b0b, b1b);
            }
        }
        __syncwarp();
    }

    // ---- epilogue: normalize + write tf32 bits [b][l][h*128+d] ----
    const float inv0 = 1.f / l_[0];
    const float inv1 = 1.f / l_[1];
    uint32_t* d0p = g_attn + ((size_t)(b * LL + row0)) * DD + h * DH + 2 * fc;
    uint32_t* d1p = g_attn + ((size_t)(b * LL + row0 + 8)) * DD + h * DH + 2 * fc;
#pragma unroll
    for (int nf = 0; nf < 16; nf++) {
        *(uint2*)(d0p + 8 * nf) = make_uint2(f2tf32(oacc[nf][0] * inv0),
                                             f2tf32(oacc[nf][1] * inv0));
        *(uint2*)(d1p + 8 * nf) = make_uint2(f2tf32(oacc[nf][2] * inv1),
                                             f2tf32(oacc[nf][3] * inv1));
    }
}

// ---------------- launch ----------------
extern "C" void kernel_launch(void* const* d_in, const int* in_sizes, int n_in,
                              void* d_out, int out_size)
{
    const float* x     = (const float*)d_in[0];
    const float* Wq    = (const float*)d_in[1];
    const float* Wk    = (const float*)d_in[2];
    const float* Wv    = (const float*)d_in[3];
    const float* Wout  = (const float*)d_in[4];
    const float* scale = (const float*)d_in[5];
    float* out = (float*)d_out;

    float *qp, *kp;
    uint32_t *vp, *ap, *xc, *wqc, *wkc, *wvc, *woc;
    cudaGetSymbolAddress((void**)&qp,  g_q);
    cudaGetSymbolAddress((void**)&kp,  g_k);
    cudaGetSymbolAddress((void**)&vp,  g_v);
    cudaGetSymbolAddress((void**)&ap,  g_attn);
    cudaGetSymbolAddress((void**)&xc,  g_xc);
    cudaGetSymbolAddress((void**)&wqc, g_wqc);
    cudaGetSymbolAddress((void**)&wkc, g_wkc);
    cudaGetSymbolAddress((void**)&wvc, g_wvc);
    cudaGetSymbolAddress((void**)&woc, g_woc);

    build_invf_kernel<<<1, 64>>>();

    const int M = BB * LL;           // 4096
    const int XN4 = (M * DD) / 4;
    cvt_kernel<<<XN4 / 256, 256>>>(x, xc, XN4);
    dim3 tgrid(DD / 32, DD / 32);
    cvt_t_kernel<<<tgrid, 256>>>(Wq, wqc);
    cvt_t_kernel<<<tgrid, 256>>>(Wk, wkc);
    cvt_t_kernel<<<tgrid, 256>>>(Wv, wvc);
    cvt_t_kernel<<<tgrid, 256>>>(Wout, woc);

    cudaFuncSetAttribute(mma_gemm_kernel<0>, cudaFuncAttributeMaxDynamicSharedMemorySize,
                         GEMM_SMEM_BYTES);
    cudaFuncSetAttribute(mma_gemm_kernel<1>, cudaFuncAttributeMaxDynamicSharedMemorySize,
                         GEMM_SMEM_BYTES);
    cudaFuncSetAttribute(attn_mma_kernel, cudaFuncAttributeMaxDynamicSharedMemorySize,
                         ATTN2_BYTES);

    // fused QKV: grid.x = 48 (16 n-blocks x 3 matrices)
    mma_gemm_kernel<1><<<dim3(48, M / 128), 256, GEMM_SMEM_BYTES>>>(
        xc, wqc, wkc, wvc, qp, kp, vp, nullptr, M, DD, DD);

    const int rope_blocks = (BB * HH * LL) / 8;
    rope_norm_kernel<<<rope_blocks, 256>>>(qp);
    rope_norm_kernel<<<rope_blocks, 256>>>(kp);

    attn_mma_kernel<<<dim3(LL / 128, HH, BB), 256, ATTN2_BYTES>>>(scale);

    mma_gemm_kernel<0><<<dim3(16, M / 128), 256, GEMM_SMEM_BYTES>>>(
        ap, woc, nullptr, nullptr, nullptr, nullptr, nullptr, out, M, DD, DD);
}

// round 13
// speedup vs baseline: 1.3664x; 1.0078x over previous
#include <cuda_runtime.h>
#include <cstdint>
#include <cmath>

#define BB 2
#define LL 2048
#define DD 2048
#define HH 16
#define DH 128

// ---------------- scratch ----------------
__device__ float    g_q[(size_t)BB * HH * LL * DH];     // fp32 after GEMM, tf32 bits after rope
__device__ float    g_k[(size_t)BB * HH * LL * DH];
__device__ uint32_t g_v[(size_t)BB * HH * LL * DH];     // tf32 bits, TRANSPOSED: [b][h][d][l]
__device__ uint32_t g_attn[(size_t)BB * LL * DD];       // tf32 bits
__device__ uint32_t g_xc[(size_t)BB * LL * DD];         // x as tf32 bits
__device__ uint32_t g_wqc[(size_t)DD * DD];             // W^T as tf32 bits  [n][k]
__device__ uint32_t g_wkc[(size_t)DD * DD];
__device__ uint32_t g_wvc[(size_t)DD * DD];
__device__ uint32_t g_woc[(size_t)DD * DD];
__device__ float    g_invf[64];

__global__ void build_invf_kernel() {
    int i = threadIdx.x;
    if (i < 64) {
        double e = (double)(2 * i) / 128.0;
        g_invf[i] = (float)pow(500000.0, -e);
    }
}

__device__ __forceinline__ uint32_t smem_u32(const void* p) {
    uint32_t a;
    asm("{ .reg .u64 t; cvta.to.shared.u64 t, %1; cvt.u32.u64 %0, t; }"
        : "=r"(a) : "l"(p));
    return a;
}

__device__ __forceinline__ uint32_t f2tf32(float f) {
    uint32_t u;
    asm("cvt.rna.tf32.f32 %0, %1;" : "=r"(u) : "f"(f));
    return u;
}

__device__ __forceinline__ float fast_exp2(float x) {
    float r;
    asm("ex2.approx.ftz.f32 %0, %1;" : "=f"(r) : "f"(x));
    return r;
}

#define MMA_TF32(acc, a0, a1, a2, a3, b0, b1)                                 \
    asm volatile(                                                             \
        "mma.sync.aligned.m16n8k8.row.col.f32.tf32.tf32.f32 "                 \
        "{%0,%1,%2,%3}, {%4,%5,%6,%7}, {%8,%9}, {%0,%1,%2,%3};"               \
        : "+f"((acc)[0]), "+f"((acc)[1]), "+f"((acc)[2]), "+f"((acc)[3])      \
        : "r"(a0), "r"(a1), "r"(a2), "r"(a3), "r"(b0), "r"(b1))

#define LDSM_X4(r0, r1, r2, r3, addr)                                         \
    asm volatile("ldmatrix.sync.aligned.m8n8.x4.shared.b16 {%0,%1,%2,%3}, [%4];" \
                 : "=r"(r0), "=r"(r1), "=r"(r2), "=r"(r3) : "r"(addr))

#define CP_ASYNC16(saddr, gptr)                                               \
    asm volatile("cp.async.cg.shared.global [%0], [%1], 16;"                  \
                 :: "r"(saddr), "l"(gptr))
#define CP_COMMIT() asm volatile("cp.async.commit_group;")
#define CP_WAIT(n)  asm volatile("cp.async.wait_group %0;" :: "n"(n))

// ---------------- fp32 -> tf32-bits converters ----------------
__global__ __launch_bounds__(256)
void cvt_kernel(const float* __restrict__ s, uint32_t* __restrict__ d, int n4)
{
    int i = blockIdx.x * 256 + threadIdx.x;
    if (i < n4) {
        float4 v = ((const float4*)s)[i];
        ((uint4*)d)[i] = make_uint4(f2tf32(v.x), f2tf32(v.y), f2tf32(v.z), f2tf32(v.w));
    }
}

// transpose + convert: W [k][n] fp32 -> Wt [n][k] tf32 bits
__global__ __launch_bounds__(256)
void cvt_t_kernel(const float* __restrict__ s, uint32_t* __restrict__ d)
{
    __shared__ uint32_t tile[32][33];
    const int tx = threadIdx.x & 31, ty = threadIdx.x >> 5;
    const int c0 = blockIdx.x * 32, r0 = blockIdx.y * 32;
#pragma unroll
    for (int i = 0; i < 4; i++)
        tile[ty + i * 8][tx] = f2tf32(s[(size_t)(r0 + ty + i * 8) * DD + c0 + tx]);
    __syncthreads();
#pragma unroll
    for (int i = 0; i < 4; i++)
        d[(size_t)(c0 + ty + i * 8) * DD + r0 + tx] = tile[tx][ty + i * 8];
}

// ============================================================================
// tf32 mma GEMM, ldmatrix feeds: C[M,N] = A[M,K] @ Bt^T  (Bt is [n][k])
// CTA 128x128, 8 warps (2m x 4n), warp 64x32.  3-stage cp.async pipeline,
// ONE __syncthreads per k-tile.
// ============================================================================
#define ASTRIDE 36
#define A_FLOATS (128 * ASTRIDE)          // 4608
#define B_FLOATS (128 * ASTRIDE)          // 4608
#define BUF_FLOATS (A_FLOATS + B_FLOATS)  // 9216
#define GEMM_SMEM_BYTES (3 * BUF_FLOATS * 4)  // 110592

template <int MODE>
__global__ __launch_bounds__(256, 2)
void mma_gemm_kernel(const uint32_t* __restrict__ A,
                     const uint32_t* __restrict__ B0,
                     const uint32_t* __restrict__ B1,
                     const uint32_t* __restrict__ B2,
                     float* __restrict__ Cq, float* __restrict__ Ck,
                     uint32_t* __restrict__ Cv, float* __restrict__ Cout,
                     int M, int N, int K)
{
    extern __shared__ __align__(16) uint32_t smu[];
    const int tid = threadIdx.x;
    const int wid = tid >> 5;
    const int lane = tid & 31;
    const int warp_m = wid >> 2;       // 0..1
    const int warp_n = wid & 3;        // 0..3
    const int by = blockIdx.y;
    int bxm = blockIdx.x, mid = 0;
    const uint32_t* Bm;
    if (MODE == 1) {
        mid = bxm >> 4;
        bxm &= 15;
        Bm = (mid == 0) ? B0 : (mid == 1) ? B1 : B2;
    } else {
        Bm = B0;
    }
    const int m0 = by * 128, n0 = bxm * 128;
    const uint32_t sbase = smem_u32(smu);
    const int fr = lane >> 2, fc = lane & 3;
    const int t3 = lane >> 3, rr = lane & 7;

    // ldmatrix per-thread row/col offsets
    const int a_row = warp_m * 64 + (t3 & 1) * 8 + rr;   // + mt*16
    const int a_col = (t3 >> 1) * 4;                      // + kb
    const int b_row = warp_n * 32 + (t3 >> 1) * 8 + rr;  // + 16 for second pair
    const int b_col = (t3 & 1) * 4;                       // + kb

    // loaders: 8 threads per row, 32 rows per pass, 4 passes
    const int l_r = tid >> 3, l_kq = tid & 7;
    const uint32_t* aG0 = A + (size_t)(m0 + l_r) * K + l_kq * 4;
    const uint32_t* bG0 = Bm + (size_t)(n0 + l_r) * K + l_kq * 4;
    const uint32_t aS0 = sbase + (uint32_t)(l_r * ASTRIDE + l_kq * 4) * 4;
    const uint32_t bS0 = sbase + (uint32_t)(A_FLOATS + l_r * ASTRIDE + l_kq * 4) * 4;

#define LOAD_TILE(kt, buf) do {                                               \
    const uint32_t off = (uint32_t)(buf) * (BUF_FLOATS * 4);                  \
    _Pragma("unroll")                                                         \
    for (int i = 0; i < 4; i++)                                               \
        CP_ASYNC16(aS0 + off + (uint32_t)(i * 32 * ASTRIDE) * 4,              \
                   aG0 + (size_t)(i * 32) * K + (kt) * 32);                   \
    _Pragma("unroll")                                                         \
    for (int i = 0; i < 4; i++)                                               \
        CP_ASYNC16(bS0 + off + (uint32_t)(i * 32 * ASTRIDE) * 4,              \
                   bG0 + (size_t)(i * 32) * K + (kt) * 32);                   \
    CP_COMMIT();                                                              \
} while (0)

    float acc[4][4][4];
#pragma unroll
    for (int mt = 0; mt < 4; mt++)
#pragma unroll
        for (int nt = 0; nt < 4; nt++)
#pragma unroll
            for (int r = 0; r < 4; r++) acc[mt][nt][r] = 0.f;

    const int KT = K / 32;
    LOAD_TILE(0, 0);
    LOAD_TILE(1, 1);

    int bufc = 0;
    for (int kt = 0; kt < KT; kt++) {
        if (kt + 1 < KT) CP_WAIT(1);
        else             CP_WAIT(0);
        __syncthreads();     // tile kt visible; everyone done reading buf (kt-1)%3
        if (kt + 2 < KT) {
            int nb = bufc + 2; if (nb >= 3) nb -= 3;
            LOAD_TILE(kt + 2, nb);
        }

        const uint32_t sA = sbase + (uint32_t)bufc * (BUF_FLOATS * 4);
        const uint32_t sB = sA + A_FLOATS * 4;

#pragma unroll
        for (int s = 0; s < 4; s++) {
            const int kb = s * 8;
            uint32_t af[4][4], bf[4][2];
#pragma unroll
            for (int mt = 0; mt < 4; mt++)
                LDSM_X4(af[mt][0], af[mt][1], af[mt][2], af[mt][3],
                        sA + (uint32_t)((a_row + mt * 16) * ASTRIDE + kb + a_col) * 4);
            LDSM_X4(bf[0][0], bf[0][1], bf[1][0], bf[1][1],
                    sB + (uint32_t)(b_row * ASTRIDE + kb + b_col) * 4);
            LDSM_X4(bf[2][0], bf[2][1], bf[3][0], bf[3][1],
                    sB + (uint32_t)((b_row + 16) * ASTRIDE + kb + b_col) * 4);
#pragma unroll
            for (int mt = 0; mt < 4; mt++)
#pragma unroll
                for (int nt = 0; nt < 4; nt++)
                    MMA_TF32(acc[mt][nt], af[mt][0], af[mt][1], af[mt][2], af[mt][3],
                             bf[nt][0], bf[nt][1]);
        }
        bufc = bufc + 1; if (bufc == 3) bufc = 0;
    }

    // epilogue
#pragma unroll
    for (int mt = 0; mt < 4; mt++) {
#pragma unroll
        for (int nt = 0; nt < 4; nt++) {
            const int r0 = m0 + warp_m * 64 + mt * 16 + fr;
            const int nloc = warp_n * 32 + nt * 8 + fc * 2;
            float2 v0 = make_float2(acc[mt][nt][0], acc[mt][nt][1]);
            float2 v1 = make_float2(acc[mt][nt][2], acc[mt][nt][3]);
            if (MODE == 1) {
                const int b0_ = r0 >> 11, l0 = r0 & 2047;
                const int b1_ = (r0 + 8) >> 11, l1 = (r0 + 8) & 2047;
                if (mid == 2) {
                    // transposed V: [b][h][d][l], tf32 bits
                    const size_t vb0 = ((size_t)(b0_ * HH + bxm) * DH + nloc) * LL;
                    const size_t vb1 = ((size_t)(b1_ * HH + bxm) * DH + nloc) * LL;
                    Cv[vb0 + l0]      = f2tf32(v0.x);
                    Cv[vb0 + LL + l0] = f2tf32(v0.y);
                    Cv[vb1 + l1]      = f2tf32(v1.x);
                    Cv[vb1 + LL + l1] = f2tf32(v1.y);
                } else {
                    float* Ct = (mid == 0) ? Cq : Ck;
                    const size_t o0 = (((size_t)(b0_ * HH + bxm)) * LL + l0) * DH + nloc;
                    const size_t o1 = (((size_t)(b1_ * HH + bxm)) * LL + l1) * DH + nloc;
                    *(float2*)(Ct + o0) = v0;
                    *(float2*)(Ct + o1) = v1;
                }
            } else {
                *(float2*)(Cout + (size_t)r0 * N + n0 + nloc) = v0;
                *(float2*)(Cout + (size_t)(r0 + 8) * N + n0 + nloc) = v1;
            }
        }
    }
#undef LOAD_TILE
}

// ---------------- RoPE + L2-normalize; writes tf32 bits in place ----------------
__global__ __launch_bounds__(256)
void rope_norm_kernel(float* __restrict__ t)
{
    const int gw = (blockIdx.x * 256 + threadIdx.x) >> 5;
    const int lane = threadIdx.x & 31;
    const int pos = gw & (LL - 1);
    float* row = t + (size_t)gw * DH;

    const float invf0 = g_invf[lane];
    const float invf1 = g_invf[lane + 32];
    const float pf = (float)pos;
    float s0, c0, s1, c1;
    sincosf(pf * invf0, &s0, &c0);
    sincosf(pf * invf1, &s1, &c1);

    float2 x = ((const float2*)row)[lane];
    float2 y = ((const float2*)row)[lane + 32];
    const float r0 = x.x * c0 - x.y * s0;
    const float r1 = x.y * c0 + x.x * s0;
    const float r2 = y.x * c1 - y.y * s1;
    const float r3 = y.y * c1 + y.x * s1;

    float ss = r0 * r0 + r1 * r1 + r2 * r2 + r3 * r3;
#pragma unroll
    for (int off = 16; off > 0; off >>= 1)
        ss += __shfl_xor_sync(0xffffffffu, ss, off);
    const float inv = 1.0f / (sqrtf(ss) + 1e-6f);

    uint32_t* rowu = (uint32_t*)row;
    ((uint2*)rowu)[lane]      = make_uint2(f2tf32(r0 * inv), f2tf32(r1 * inv));
    ((uint2*)rowu)[lane + 32] = make_uint2(f2tf32(r2 * inv), f2tf32(r3 * inv));
}

// ============================================================================
// tensor-core causal flash attention, q-tile 128, 256 threads (8 warps x 16 q)
// MAX-FREE softmax: |S|<=1 (normalized q,k) so exp2(sc2*S) is in-range;
// no running max, no rescale, per-thread l partials reduced once at the end.
// ============================================================================
#define AKS 132
#define AVS 68
#define APS 68
#define AV_OFF (64 * AKS)                  // 8448
#define AP_OFF (AV_OFF + 128 * AVS)        // 17152
#define ATTN2_U32 (AP_OFF + 128 * APS)     // 25856
#define ATTN2_BYTES (ATTN2_U32 * 4)        // 103424

__global__ __launch_bounds__(256, 1)
void attn_mma_kernel(const float* __restrict__ scale_ptr)
{
    extern __shared__ __align__(16) uint32_t smu[];
    uint32_t* k_u = smu;
    uint32_t* v_u = smu + AV_OFF;
    uint32_t* p_u = smu + AP_OFF;

    const int qt = (int)gridDim.x - 1 - (int)blockIdx.x;   // heavy tiles first
    const int h = blockIdx.y, b = blockIdx.z;
    const int tid = threadIdx.x;
    const int wid = tid >> 5, lane = tid & 31;
    const int fr = lane >> 2, fc = lane & 3;
    const int t3 = lane >> 3, rr = lane & 7;
    const float sc2 = (*scale_ptr) * 1.4426950408889634f;

    const size_t head_off = (size_t)(b * HH + h) * LL * DH;
    const uint32_t* qptr = (const uint32_t*)g_q + head_off;
    const uint32_t* kptr = (const uint32_t*)g_k + head_off;
    const uint32_t* vtptr = g_v + head_off;          // [d][l] layout
    const int q0 = qt * 128;

    const uint32_t sK = smem_u32(smu);
    const uint32_t sV = sK + AV_OFF * 4;
    const uint32_t sP = sK + AP_OFF * 4;

    const int lr = tid >> 2, lq = tid & 3;           // K/Q loader: 64 rows, 4 thr/row
    const int vr = tid >> 1, vh = tid & 1;           // V loader: 128 rows, 2 thr/row

    // ---- stage Q bits (two 64-row passes through k_s), preload A-frags ----
    uint32_t qa[16][4];
    const uint32_t qbase = sK +
        (uint32_t)(((wid & 3) * 16 + (t3 & 1) * 8 + rr) * AKS + (t3 >> 1) * 4) * 4;
    for (int pass = 0; pass < 2; pass++) {
        const uint32_t* src = qptr + (size_t)(q0 + pass * 64 + lr) * DH + lq * 32;
        uint32_t* dst = k_u + lr * AKS + lq * 32;
#pragma unroll
        for (int j = 0; j < 8; j++)
            *(uint4*)(dst + j * 4) = *(const uint4*)(src + j * 4);
        __syncthreads();
        if ((wid >> 2) == pass) {
#pragma unroll
            for (int s = 0; s < 16; s++)
                LDSM_X4(qa[s][0], qa[s][1], qa[s][2], qa[s][3],
                        qbase + (uint32_t)(s * 8) * 4);
        }
        __syncthreads();
    }

    float oacc[16][4];
#pragma unroll
    for (int nf = 0; nf < 16; nf++)
#pragma unroll
        for (int r = 0; r < 4; r++) oacc[nf][r] = 0.f;
    float l_[2] = {0.f, 0.f};    // per-thread partial row sums

    const int row0 = q0 + wid * 16 + fr;

    // ldmatrix per-thread bases
    const int kb_row = (t3 >> 1) * 8 + rr;   // + 16*jj  (K B-frags)
    const int kb_col = (t3 & 1) * 4;         // + 8*s
    const int vb_row = (t3 >> 1) * 8 + rr;   // + 16*nfp (V B-frags)
    const int vb_col = (t3 & 1) * 4;         // + 8*s2
    const int pa_row = wid * 16 + (t3 & 1) * 8 + rr;
    const int pa_col = (t3 >> 1) * 4;        // + 8*s2

    const int KTend = 2 * qt + 1;
    for (int kt = 0; kt <= KTend; kt++) {
        const int k0 = kt * 64;
        __syncthreads();
        {
            // K: [kpos][d] rows, coalesced (64 rows x 128)
            const uint32_t* ksrc = kptr + (size_t)(k0 + lr) * DH + lq * 32;
            uint32_t* kdst = k_u + lr * AKS + lq * 32;
#pragma unroll
            for (int j = 0; j < 8; j++)
                *(uint4*)(kdst + j * 4) = *(const uint4*)(ksrc + j * 4);
            // V: gmem [d][l] rows -> smem [d][kpos] rows (128 rows x 64)
            const uint32_t* vsrc = vtptr + (size_t)vr * LL + k0 + vh * 32;
            uint32_t* vdst = v_u + vr * AVS + vh * 32;
#pragma unroll
            for (int j = 0; j < 8; j++)
                *(uint4*)(vdst + j * 4) = *(const uint4*)(vsrc + j * 4);
        }
        __syncthreads();

        // ---- S = Q K^T ----
        float sacc[8][4];
#pragma unroll
        for (int j = 0; j < 8; j++)
#pragma unroll
            for (int r = 0; r < 4; r++) sacc[j][r] = 0.f;

#pragma unroll
        for (int s = 0; s < 16; s++) {
#pragma unroll
            for (int jj = 0; jj < 4; jj++) {
                uint32_t b0a, b1a, b0b, b1b;
                LDSM_X4(b0a, b1a, b0b, b1b,
                        sK + (uint32_t)((jj * 16 + kb_row) * AKS + s * 8 + kb_col) * 4);
                MMA_TF32(sacc[2 * jj],     qa[s][0], qa[s][1], qa[s][2], qa[s][3], b0a, b1a);
                MMA_TF32(sacc[2 * jj + 1], qa[s][0], qa[s][1], qa[s][2], qa[s][3], b0b, b1b);
            }
        }

        // ---- mask (last two k-tiles straddle the diagonal) ----
        if (kt >= 2 * qt) {
#pragma unroll
            for (int j = 0; j < 8; j++) {
                const int c0 = k0 + 8 * j + 2 * fc;
                if (c0 > row0)     sacc[j][0] = -1e30f;
                if (c0 + 1 > row0) sacc[j][1] = -1e30f;
                if (c0 > row0 + 8)     sacc[j][2] = -1e30f;
                if (c0 + 1 > row0 + 8) sacc[j][3] = -1e30f;
            }
        }

        // ---- max-free softmax: p = exp2(sc2 * s) ----
#pragma unroll
        for (int r2 = 0; r2 < 2; r2++) {
            uint32_t* prow = p_u + (wid * 16 + fr + 8 * r2) * APS + 2 * fc;
            float rs = 0.f;
#pragma unroll
            for (int j = 0; j < 8; j++) {
                float p0 = fast_exp2(sc2 * sacc[j][2 * r2]);
                float p1 = fast_exp2(sc2 * sacc[j][2 * r2 + 1]);
                rs += p0 + p1;
                *(uint2*)(prow + 8 * j) = make_uint2(f2tf32(p0), f2tf32(p1));
            }
            l_[r2] += rs;
        }
        __syncwarp();

        // ---- O += P V ----
#pragma unroll
        for (int s2 = 0; s2 < 8; s2++) {
            uint32_t a0, a1, a2, a3;
            LDSM_X4(a0, a1, a2, a3,
                    sP + (uint32_t)(pa_row * APS + s2 * 8 + pa_col) * 4);
#pragma unroll
            for (int nfp = 0; nfp < 8; nfp++) {
                uint32_t b0a, b1a, b0b, b1b;
                LDSM_X4(b0a, b1a, b0b, b1b,
                        sV + (uint32_t)((nfp * 16 + vb_row) * AVS + s2 * 8 + vb_col) * 4);
                MMA_TF32(oacc[2 * nfp],     a0, a1, a2, a3, b0a, b1a);
                MMA_TF32(oacc[2 * nfp + 1], a0, a1, a2, a3, b0b, b1b);
            }
        }
        __syncwarp();
    }

    // ---- reduce row sums across the quad (lanes differing in bits 0,1) ----
    float l0 = l_[0], l1 = l_[1];
    l0 += __shfl_xor_sync(0xffffffffu, l0, 1);
    l0 += __shfl_xor_sync(0xffffffffu, l0, 2);
    l1 += __shfl_xor_sync(0xffffffffu, l1, 1);
    l1 += __shfl_xor_sync(0xffffffffu, l1, 2);

    // ---- epilogue: normalize + write tf32 bits [b][l][h*128+d] ----
    const float inv0 = 1.f / l0;
    const float inv1 = 1.f / l1;
    uint32_t* d0p = g_attn + ((size_t)(b * LL + row0)) * DD + h * DH + 2 * fc;
    uint32_t* d1p = g_attn + ((size_t)(b * LL + row0 + 8)) * DD + h * DH + 2 * fc;
#pragma unroll
    for (int nf = 0; nf < 16; nf++) {
        *(uint2*)(d0p + 8 * nf) = make_uint2(f2tf32(oacc[nf][0] * inv0),
                                             f2tf32(oacc[nf][1] * inv0));
        *(uint2*)(d1p + 8 * nf) = make_uint2(f2tf32(oacc[nf][2] * inv1),
                                             f2tf32(oacc[nf][3] * inv1));
    }
}

// ---------------- launch ----------------
extern "C" void kernel_launch(void* const* d_in, const int* in_sizes, int n_in,
                              void* d_out, int out_size)
{
    const float* x     = (const float*)d_in[0];
    const float* Wq    = (const float*)d_in[1];
    const float* Wk    = (const float*)d_in[2];
    const float* Wv    = (const float*)d_in[3];
    const float* Wout  = (const float*)d_in[4];
    const float* scale = (const float*)d_in[5];
    float* out = (float*)d_out;

    float *qp, *kp;
    uint32_t *vp, *ap, *xc, *wqc, *wkc, *wvc, *woc;
    cudaGetSymbolAddress((void**)&qp,  g_q);
    cudaGetSymbolAddress((void**)&kp,  g_k);
    cudaGetSymbolAddress((void**)&vp,  g_v);
    cudaGetSymbolAddress((void**)&ap,  g_attn);
    cudaGetSymbolAddress((void**)&xc,  g_xc);
    cudaGetSymbolAddress((void**)&wqc, g_wqc);
    cudaGetSymbolAddress((void**)&wkc, g_wkc);
    cudaGetSymbolAddress((void**)&wvc, g_wvc);
    cudaGetSymbolAddress((void**)&woc, g_woc);

    build_invf_kernel<<<1, 64>>>();

    const int M = BB * LL;           // 4096
    const int XN4 = (M * DD) / 4;
    cvt_kernel<<<XN4 / 256, 256>>>(x, xc, XN4);
    dim3 tgrid(DD / 32, DD / 32);
    cvt_t_kernel<<<tgrid, 256>>>(Wq, wqc);
    cvt_t_kernel<<<tgrid, 256>>>(Wk, wkc);
    cvt_t_kernel<<<tgrid, 256>>>(Wv, wvc);
    cvt_t_kernel<<<tgrid, 256>>>(Wout, woc);

    cudaFuncSetAttribute(mma_gemm_kernel<0>, cudaFuncAttributeMaxDynamicSharedMemorySize,
                         GEMM_SMEM_BYTES);
    cudaFuncSetAttribute(mma_gemm_kernel<1>, cudaFuncAttributeMaxDynamicSharedMemorySize,
                         GEMM_SMEM_BYTES);
    cudaFuncSetAttribute(attn_mma_kernel, cudaFuncAttributeMaxDynamicSharedMemorySize,
                         ATTN2_BYTES);

    // fused QKV: grid.x = 48 (16 n-blocks x 3 matrices)
    mma_gemm_kernel<1><<<dim3(48, M / 128), 256, GEMM_SMEM_BYTES>>>(
        xc, wqc, wkc, wvc, qp, kp, vp, nullptr, M, DD, DD);

    const int rope_blocks = (BB * HH * LL) / 8;
    rope_norm_kernel<<<rope_blocks, 256>>>(qp);
    rope_norm_kernel<<<rope_blocks, 256>>>(kp);

    attn_mma_kernel<<<dim3(LL / 128, HH, BB), 256, ATTN2_BYTES>>>(scale);

    mma_gemm_kernel<0><<<dim3(16, M / 128), 256, GEMM_SMEM_BYTES>>>(
        ap, woc, nullptr, nullptr, nullptr, nullptr, nullptr, out, M, DD, DD);
}

// round 14
// speedup vs baseline: 1.4660x; 1.0729x over previous
#include <cuda_runtime.h>
#include <cstdint>
#include <cmath>

#define BB 2
#define LL 2048
#define DD 2048
#define HH 16
#define DH 128

// ---------------- scratch ----------------
__device__ float    g_q[(size_t)BB * HH * LL * DH];     // fp32 after GEMM, tf32 bits after rope
__device__ float    g_k[(size_t)BB * HH * LL * DH];
__device__ uint32_t g_v[(size_t)BB * HH * LL * DH];     // tf32 bits, TRANSPOSED: [b][h][d][l]
__device__ uint32_t g_attn[(size_t)BB * LL * DD];       // tf32 bits
__device__ uint32_t g_xc[(size_t)BB * LL * DD];         // x as tf32 bits
__device__ uint32_t g_wqc[(size_t)DD * DD];             // W^T as tf32 bits  [n][k]
__device__ uint32_t g_wkc[(size_t)DD * DD];
__device__ uint32_t g_wvc[(size_t)DD * DD];
__device__ uint32_t g_woc[(size_t)DD * DD];
__device__ float    g_invf[64];

__global__ void build_invf_kernel() {
    int i = threadIdx.x;
    if (i < 64) {
        double e = (double)(2 * i) / 128.0;
        g_invf[i] = (float)pow(500000.0, -e);
    }
}

__device__ __forceinline__ uint32_t smem_u32(const void* p) {
    uint32_t a;
    asm("{ .reg .u64 t; cvta.to.shared.u64 t, %1; cvt.u32.u64 %0, t; }"
        : "=r"(a) : "l"(p));
    return a;
}

__device__ __forceinline__ uint32_t f2tf32(float f) {
    uint32_t u;
    asm("cvt.rna.tf32.f32 %0, %1;" : "=r"(u) : "f"(f));
    return u;
}

__device__ __forceinline__ float fast_exp2(float x) {
    float r;
    asm("ex2.approx.ftz.f32 %0, %1;" : "=f"(r) : "f"(x));
    return r;
}

#define MMA_TF32(acc, a0, a1, a2, a3, b0, b1)                                 \
    asm volatile(                                                             \
        "mma.sync.aligned.m16n8k8.row.col.f32.tf32.tf32.f32 "                 \
        "{%0,%1,%2,%3}, {%4,%5,%6,%7}, {%8,%9}, {%0,%1,%2,%3};"               \
        : "+f"((acc)[0]), "+f"((acc)[1]), "+f"((acc)[2]), "+f"((acc)[3])      \
        : "r"(a0), "r"(a1), "r"(a2), "r"(a3), "r"(b0), "r"(b1))

#define LDSM_X4(r0, r1, r2, r3, addr)                                         \
    asm volatile("ldmatrix.sync.aligned.m8n8.x4.shared.b16 {%0,%1,%2,%3}, [%4];" \
                 : "=r"(r0), "=r"(r1), "=r"(r2), "=r"(r3) : "r"(addr))

#define CP_ASYNC16(saddr, gptr)                                               \
    asm volatile("cp.async.cg.shared.global [%0], [%1], 16;"                  \
                 :: "r"(saddr), "l"(gptr))
#define CP_COMMIT() asm volatile("cp.async.commit_group;")
#define CP_WAIT(n)  asm volatile("cp.async.wait_group %0;" :: "n"(n))

// ---------------- fp32 -> tf32-bits converters ----------------
__global__ __launch_bounds__(256)
void cvt_kernel(const float* __restrict__ s, uint32_t* __restrict__ d, int n4)
{
    int i = blockIdx.x * 256 + threadIdx.x;
    if (i < n4) {
        float4 v = ((const float4*)s)[i];
        ((uint4*)d)[i] = make_uint4(f2tf32(v.x), f2tf32(v.y), f2tf32(v.z), f2tf32(v.w));
    }
}

// transpose + convert: W [k][n] fp32 -> Wt [n][k] tf32 bits
__global__ __launch_bounds__(256)
void cvt_t_kernel(const float* __restrict__ s, uint32_t* __restrict__ d)
{
    __shared__ uint32_t tile[32][33];
    const int tx = threadIdx.x & 31, ty = threadIdx.x >> 5;
    const int c0 = blockIdx.x * 32, r0 = blockIdx.y * 32;
#pragma unroll
    for (int i = 0; i < 4; i++)
        tile[ty + i * 8][tx] = f2tf32(s[(size_t)(r0 + ty + i * 8) * DD + c0 + tx]);
    __syncthreads();
#pragma unroll
    for (int i = 0; i < 4; i++)
        d[(size_t)(c0 + ty + i * 8) * DD + r0 + tx] = tile[tx][ty + i * 8];
}

// ============================================================================
// tf32 mma GEMM, ldmatrix feeds: C[M,N] = A[M,K] @ Bt^T  (Bt is [n][k])
// CTA 128x128, 8 warps (2m x 4n), warp 64x32.  3-stage cp.async pipeline.
// ============================================================================
#define ASTRIDE 36
#define A_FLOATS (128 * ASTRIDE)          // 4608
#define B_FLOATS (128 * ASTRIDE)          // 4608
#define BUF_FLOATS (A_FLOATS + B_FLOATS)  // 9216
#define GEMM_SMEM_BYTES (3 * BUF_FLOATS * 4)  // 110592

template <int MODE>
__global__ __launch_bounds__(256, 2)
void mma_gemm_kernel(const uint32_t* __restrict__ A,
                     const uint32_t* __restrict__ B0,
                     const uint32_t* __restrict__ B1,
                     const uint32_t* __restrict__ B2,
                     float* __restrict__ Cq, float* __restrict__ Ck,
                     uint32_t* __restrict__ Cv, float* __restrict__ Cout,
                     int M, int N, int K)
{
    extern __shared__ __align__(16) uint32_t smu[];
    const int tid = threadIdx.x;
    const int wid = tid >> 5;
    const int lane = tid & 31;
    const int warp_m = wid >> 2;       // 0..1
    const int warp_n = wid & 3;        // 0..3
    const int by = blockIdx.y;
    int bxm = blockIdx.x, mid = 0;
    const uint32_t* Bm;
    if (MODE == 1) {
        mid = bxm >> 4;
        bxm &= 15;
        Bm = (mid == 0) ? B0 : (mid == 1) ? B1 : B2;
    } else {
        Bm = B0;
    }
    const int m0 = by * 128, n0 = bxm * 128;
    const uint32_t sbase = smem_u32(smu);
    const int fr = lane >> 2, fc = lane & 3;
    const int t3 = lane >> 3, rr = lane & 7;

    const int a_row = warp_m * 64 + (t3 & 1) * 8 + rr;
    const int a_col = (t3 >> 1) * 4;
    const int b_row = warp_n * 32 + (t3 >> 1) * 8 + rr;
    const int b_col = (t3 & 1) * 4;

    const int l_r = tid >> 3, l_kq = tid & 7;
    const uint32_t* aG0 = A + (size_t)(m0 + l_r) * K + l_kq * 4;
    const uint32_t* bG0 = Bm + (size_t)(n0 + l_r) * K + l_kq * 4;
    const uint32_t aS0 = sbase + (uint32_t)(l_r * ASTRIDE + l_kq * 4) * 4;
    const uint32_t bS0 = sbase + (uint32_t)(A_FLOATS + l_r * ASTRIDE + l_kq * 4) * 4;

#define LOAD_TILE(kt, buf) do {                                               \
    const uint32_t off = (uint32_t)(buf) * (BUF_FLOATS * 4);                  \
    _Pragma("unroll")                                                         \
    for (int i = 0; i < 4; i++)                                               \
        CP_ASYNC16(aS0 + off + (uint32_t)(i * 32 * ASTRIDE) * 4,              \
                   aG0 + (size_t)(i * 32) * K + (kt) * 32);                   \
    _Pragma("unroll")                                                         \
    for (int i = 0; i < 4; i++)                                               \
        CP_ASYNC16(bS0 + off + (uint32_t)(i * 32 * ASTRIDE) * 4,              \
                   bG0 + (size_t)(i * 32) * K + (kt) * 32);                   \
    CP_COMMIT();                                                              \
} while (0)

    float acc[4][4][4];
#pragma unroll
    for (int mt = 0; mt < 4; mt++)
#pragma unroll
        for (int nt = 0; nt < 4; nt++)
#pragma unroll
            for (int r = 0; r < 4; r++) acc[mt][nt][r] = 0.f;

    const int KT = K / 32;
    LOAD_TILE(0, 0);
    LOAD_TILE(1, 1);

    int bufc = 0;
    for (int kt = 0; kt < KT; kt++) {
        if (kt + 1 < KT) CP_WAIT(1);
        else             CP_WAIT(0);
        __syncthreads();
        if (kt + 2 < KT) {
            int nb = bufc + 2; if (nb >= 3) nb -= 3;
            LOAD_TILE(kt + 2, nb);
        }

        const uint32_t sA = sbase + (uint32_t)bufc * (BUF_FLOATS * 4);
        const uint32_t sB = sA + A_FLOATS * 4;

#pragma unroll
        for (int s = 0; s < 4; s++) {
            const int kb = s * 8;
            uint32_t af[4][4], bf[4][2];
#pragma unroll
            for (int mt = 0; mt < 4; mt++)
                LDSM_X4(af[mt][0], af[mt][1], af[mt][2], af[mt][3],
                        sA + (uint32_t)((a_row + mt * 16) * ASTRIDE + kb + a_col) * 4);
            LDSM_X4(bf[0][0], bf[0][1], bf[1][0], bf[1][1],
                    sB + (uint32_t)(b_row * ASTRIDE + kb + b_col) * 4);
            LDSM_X4(bf[2][0], bf[2][1], bf[3][0], bf[3][1],
                    sB + (uint32_t)((b_row + 16) * ASTRIDE + kb + b_col) * 4);
#pragma unroll
            for (int mt = 0; mt < 4; mt++)
#pragma unroll
                for (int nt = 0; nt < 4; nt++)
                    MMA_TF32(acc[mt][nt], af[mt][0], af[mt][1], af[mt][2], af[mt][3],
                             bf[nt][0], bf[nt][1]);
        }
        bufc = bufc + 1; if (bufc == 3) bufc = 0;
    }

    // epilogue
#pragma unroll
    for (int mt = 0; mt < 4; mt++) {
#pragma unroll
        for (int nt = 0; nt < 4; nt++) {
            const int r0 = m0 + warp_m * 64 + mt * 16 + fr;
            const int nloc = warp_n * 32 + nt * 8 + fc * 2;
            float2 v0 = make_float2(acc[mt][nt][0], acc[mt][nt][1]);
            float2 v1 = make_float2(acc[mt][nt][2], acc[mt][nt][3]);
            if (MODE == 1) {
                const int b0_ = r0 >> 11, l0 = r0 & 2047;
                const int b1_ = (r0 + 8) >> 11, l1 = (r0 + 8) & 2047;
                if (mid == 2) {
                    const size_t vb0 = ((size_t)(b0_ * HH + bxm) * DH + nloc) * LL;
                    const size_t vb1 = ((size_t)(b1_ * HH + bxm) * DH + nloc) * LL;
                    Cv[vb0 + l0]      = f2tf32(v0.x);
                    Cv[vb0 + LL + l0] = f2tf32(v0.y);
                    Cv[vb1 + l1]      = f2tf32(v1.x);
                    Cv[vb1 + LL + l1] = f2tf32(v1.y);
                } else {
                    float* Ct = (mid == 0) ? Cq : Ck;
                    const size_t o0 = (((size_t)(b0_ * HH + bxm)) * LL + l0) * DH + nloc;
                    const size_t o1 = (((size_t)(b1_ * HH + bxm)) * LL + l1) * DH + nloc;
                    *(float2*)(Ct + o0) = v0;
                    *(float2*)(Ct + o1) = v1;
                }
            } else {
                *(float2*)(Cout + (size_t)r0 * N + n0 + nloc) = v0;
                *(float2*)(Cout + (size_t)(r0 + 8) * N + n0 + nloc) = v1;
            }
        }
    }
#undef LOAD_TILE
}

// ---------------- RoPE + L2-normalize; writes tf32 bits in place ----------------
__global__ __launch_bounds__(256)
void rope_norm_kernel(float* __restrict__ t)
{
    const int gw = (blockIdx.x * 256 + threadIdx.x) >> 5;
    const int lane = threadIdx.x & 31;
    const int pos = gw & (LL - 1);
    float* row = t + (size_t)gw * DH;

    const float invf0 = g_invf[lane];
    const float invf1 = g_invf[lane + 32];
    const float pf = (float)pos;
    float s0, c0, s1, c1;
    sincosf(pf * invf0, &s0, &c0);
    sincosf(pf * invf1, &s1, &c1);

    float2 x = ((const float2*)row)[lane];
    float2 y = ((const float2*)row)[lane + 32];
    const float r0 = x.x * c0 - x.y * s0;
    const float r1 = x.y * c0 + x.x * s0;
    const float r2 = y.x * c1 - y.y * s1;
    const float r3 = y.y * c1 + y.x * s1;

    float ss = r0 * r0 + r1 * r1 + r2 * r2 + r3 * r3;
#pragma unroll
    for (int off = 16; off > 0; off >>= 1)
        ss += __shfl_xor_sync(0xffffffffu, ss, off);
    const float inv = 1.0f / (sqrtf(ss) + 1e-6f);

    uint32_t* rowu = (uint32_t*)row;
    ((uint2*)rowu)[lane]      = make_uint2(f2tf32(r0 * inv), f2tf32(r1 * inv));
    ((uint2*)rowu)[lane + 32] = make_uint2(f2tf32(r2 * inv), f2tf32(r3 * inv));
}

// ============================================================================
// tensor-core causal flash attention, q-tile 128, 256 threads (8 warps x 16 q)
// MAX-FREE softmax.  cp.async DOUBLE-BUFFERED K/V: one __syncthreads per
// k-tile; loads of kt+1 overlap compute of kt.
// ============================================================================
#define AKS 132
#define AVS 68
#define APS 68
#define KBUF (64 * AKS)                    // 8448 u32 per K buffer
#define VBUF (128 * AVS)                   // 8704 u32 per V buffer
#define VB0 (2 * KBUF)                     // 16896
#define PB  (VB0 + 2 * VBUF)               // 34304
#define ATTN2_U32 (PB + 128 * APS)         // 43008
#define ATTN2_BYTES (ATTN2_U32 * 4)        // 172032

__global__ __launch_bounds__(256, 1)
void attn_mma_kernel(const float* __restrict__ scale_ptr)
{
    extern __shared__ __align__(16) uint32_t smu[];
    uint32_t* k_u = smu;                     // Q staging uses K buffer 0

    const int qt = (int)gridDim.x - 1 - (int)blockIdx.x;   // heavy tiles first
    const int h = blockIdx.y, b = blockIdx.z;
    const int tid = threadIdx.x;
    const int wid = tid >> 5, lane = tid & 31;
    const int fr = lane >> 2, fc = lane & 3;
    const int t3 = lane >> 3, rr = lane & 7;
    const float sc2 = (*scale_ptr) * 1.4426950408889634f;

    const size_t head_off = (size_t)(b * HH + h) * LL * DH;
    const uint32_t* qptr = (const uint32_t*)g_q + head_off;
    const uint32_t* kptr = (const uint32_t*)g_k + head_off;
    const uint32_t* vtptr = g_v + head_off;          // [d][l] layout
    const int q0 = qt * 128;

    const uint32_t sK = smem_u32(smu);
    const uint32_t sP = sK + (uint32_t)PB * 4;

    const int lr = tid >> 2, lq = tid & 3;           // K/Q loader: 64 rows, 4 thr/row
    const int vr = tid >> 1, vh = tid & 1;           // V loader: 128 rows, 2 thr/row

    const uint32_t kslot = (uint32_t)(lr * AKS + lq * 32) * 4;
    const uint32_t vslot = (uint32_t)(vr * AVS + vh * 32) * 4;
    const uint32_t kbufa[2] = {sK + kslot, sK + (uint32_t)KBUF * 4 + kslot};
    const uint32_t vbufa[2] = {sK + (uint32_t)VB0 * 4 + vslot,
                               sK + (uint32_t)(VB0 + VBUF) * 4 + vslot};

#define LOAD_KV(kt, bs) do {                                                  \
    const uint32_t* ksrc = kptr + (size_t)((kt) * 64 + lr) * DH + lq * 32;    \
    const uint32_t* vsrc = vtptr + (size_t)vr * LL + (kt) * 64 + vh * 32;     \
    _Pragma("unroll")                                                         \
    for (int j = 0; j < 8; j++)                                               \
        CP_ASYNC16(kbufa[bs] + (uint32_t)(j * 16), ksrc + j * 4);             \
    _Pragma("unroll")                                                         \
    for (int j = 0; j < 8; j++)                                               \
        CP_ASYNC16(vbufa[bs] + (uint32_t)(j * 16), vsrc + j * 4);             \
    CP_COMMIT();                                                              \
} while (0)

    // ---- stage Q bits (two 64-row passes through K buffer 0), preload A-frags ----
    uint32_t qa[16][4];
    const uint32_t qbase = sK +
        (uint32_t)(((wid & 3) * 16 + (t3 & 1) * 8 + rr) * AKS + (t3 >> 1) * 4) * 4;
    for (int pass = 0; pass < 2; pass++) {
        const uint32_t* src = qptr + (size_t)(q0 + pass * 64 + lr) * DH + lq * 32;
        uint32_t* dst = k_u + lr * AKS + lq * 32;
#pragma unroll
        for (int j = 0; j < 8; j++)
            *(uint4*)(dst + j * 4) = *(const uint4*)(src + j * 4);
        __syncthreads();
        if ((wid >> 2) == pass) {
#pragma unroll
            for (int s = 0; s < 16; s++)
                LDSM_X4(qa[s][0], qa[s][1], qa[s][2], qa[s][3],
                        qbase + (uint32_t)(s * 8) * 4);
        }
        __syncthreads();
    }

    float oacc[16][4];
#pragma unroll
    for (int nf = 0; nf < 16; nf++)
#pragma unroll
        for (int r = 0; r < 4; r++) oacc[nf][r] = 0.f;
    float l_[2] = {0.f, 0.f};

    const int row0 = q0 + wid * 16 + fr;

    // ldmatrix per-thread bases
    const int kb_row = (t3 >> 1) * 8 + rr;
    const int kb_col = (t3 & 1) * 4;
    const int vb_row = (t3 >> 1) * 8 + rr;
    const int vb_col = (t3 & 1) * 4;
    const int pa_row = wid * 16 + (t3 & 1) * 8 + rr;
    const int pa_col = (t3 >> 1) * 4;

    const int KTend = 2 * qt + 1;
    LOAD_KV(0, 0);
    int buf = 0;

    for (int kt = 0; kt <= KTend; kt++) {
        const int k0 = kt * 64;
        CP_WAIT(0);          // tile kt landed (only group in flight)
        __syncthreads();     // visibility + all warps done reading other buffer
        if (kt < KTend)
            LOAD_KV(kt + 1, buf ^ 1);   // overlaps with compute below

        const uint32_t sKb = sK + (buf ? (uint32_t)KBUF * 4 : 0u);
        const uint32_t sVb = sK + (buf ? (uint32_t)(VB0 + VBUF) * 4
                                       : (uint32_t)VB0 * 4);

        // ---- S = Q K^T ----
        float sacc[8][4];
#pragma unroll
        for (int j = 0; j < 8; j++)
#pragma unroll
            for (int r = 0; r < 4; r++) sacc[j][r] = 0.f;

#pragma unroll
        for (int s = 0; s < 16; s++) {
#pragma unroll
            for (int jj = 0; jj < 4; jj++) {
                uint32_t b0a, b1a, b0b, b1b;
                LDSM_X4(b0a, b1a, b0b, b1b,
                        sKb + (uint32_t)((jj * 16 + kb_row) * AKS + s * 8 + kb_col) * 4);
                MMA_TF32(sacc[2 * jj],     qa[s][0], qa[s][1], qa[s][2], qa[s][3], b0a, b1a);
                MMA_TF32(sacc[2 * jj + 1], qa[s][0], qa[s][1], qa[s][2], qa[s][3], b0b, b1b);
            }
        }

        // ---- mask (last two k-tiles straddle the diagonal) ----
        if (kt >= 2 * qt) {
#pragma unroll
            for (int j = 0; j < 8; j++) {
                const int c0 = k0 + 8 * j + 2 * fc;
                if (c0 > row0)     sacc[j][0] = -1e30f;
                if (c0 + 1 > row0) sacc[j][1] = -1e30f;
                if (c0 > row0 + 8)     sacc[j][2] = -1e30f;
                if (c0 + 1 > row0 + 8) sacc[j][3] = -1e30f;
            }
        }

        // ---- max-free softmax: p = exp2(sc2 * s) ----
#pragma unroll
        for (int r2 = 0; r2 < 2; r2++) {
            uint32_t* prow = (uint32_t*)smu + PB + (wid * 16 + fr + 8 * r2) * APS + 2 * fc;
            float rs = 0.f;
#pragma unroll
            for (int j = 0; j < 8; j++) {
                float p0 = fast_exp2(sc2 * sacc[j][2 * r2]);
                float p1 = fast_exp2(sc2 * sacc[j][2 * r2 + 1]);
                rs += p0 + p1;
                *(uint2*)(prow + 8 * j) = make_uint2(f2tf32(p0), f2tf32(p1));
            }
            l_[r2] += rs;
        }
        __syncwarp();

        // ---- O += P V ----
#pragma unroll
        for (int s2 = 0; s2 < 8; s2++) {
            uint32_t a0, a1, a2, a3;
            LDSM_X4(a0, a1, a2, a3,
                    sP + (uint32_t)(pa_row * APS + s2 * 8 + pa_col) * 4);
#pragma unroll
            for (int nfp = 0; nfp < 8; nfp++) {
                uint32_t b0a, b1a, b0b, b1b;
                LDSM_X4(b0a, b1a, b0b, b1b,
                        sVb + (uint32_t)((nfp * 16 + vb_row) * AVS + s2 * 8 + vb_col) * 4);
                MMA_TF32(oacc[2 * nfp],     a0, a1, a2, a3, b0a, b1a);
                MMA_TF32(oacc[2 * nfp + 1], a0, a1, a2, a3, b0b, b1b);
            }
        }
        __syncwarp();
        buf ^= 1;
    }
#undef LOAD_KV

    // ---- reduce row sums across the quad ----
    float l0 = l_[0], l1 = l_[1];
    l0 += __shfl_xor_sync(0xffffffffu, l0, 1);
    l0 += __shfl_xor_sync(0xffffffffu, l0, 2);
    l1 += __shfl_xor_sync(0xffffffffu, l1, 1);
    l1 += __shfl_xor_sync(0xffffffffu, l1, 2);

    // ---- epilogue: normalize + write tf32 bits [b][l][h*128+d] ----
    const float inv0 = 1.f / l0;
    const float inv1 = 1.f / l1;
    uint32_t* d0p = g_attn + ((size_t)(b * LL + row0)) * DD + h * DH + 2 * fc;
    uint32_t* d1p = g_attn + ((size_t)(b * LL + row0 + 8)) * DD + h * DH + 2 * fc;
#pragma unroll
    for (int nf = 0; nf < 16; nf++) {
        *(uint2*)(d0p + 8 * nf) = make_uint2(f2tf32(oacc[nf][0] * inv0),
                                             f2tf32(oacc[nf][1] * inv0));
        *(uint2*)(d1p + 8 * nf) = make_uint2(f2tf32(oacc[nf][2] * inv1),
                                             f2tf32(oacc[nf][3] * inv1));
    }
}

// ---------------- launch ----------------
extern "C" void kernel_launch(void* const* d_in, const int* in_sizes, int n_in,
                              void* d_out, int out_size)
{
    const float* x     = (const float*)d_in[0];
    const float* Wq    = (const float*)d_in[1];
    const float* Wk    = (const float*)d_in[2];
    const float* Wv    = (const float*)d_in[3];
    const float* Wout  = (const float*)d_in[4];
    const float* scale = (const float*)d_in[5];
    float* out = (float*)d_out;

    float *qp, *kp;
    uint32_t *vp, *ap, *xc, *wqc, *wkc, *wvc, *woc;
    cudaGetSymbolAddress((void**)&qp,  g_q);
    cudaGetSymbolAddress((void**)&kp,  g_k);
    cudaGetSymbolAddress((void**)&vp,  g_v);
    cudaGetSymbolAddress((void**)&ap,  g_attn);
    cudaGetSymbolAddress((void**)&xc,  g_xc);
    cudaGetSymbolAddress((void**)&wqc, g_wqc);
    cudaGetSymbolAddress((void**)&wkc, g_wkc);
    cudaGetSymbolAddress((void**)&wvc, g_wvc);
    cudaGetSymbolAddress((void**)&woc, g_woc);

    build_invf_kernel<<<1, 64>>>();

    const int M = BB * LL;           // 4096
    const int XN4 = (M * DD) / 4;
    cvt_kernel<<<XN4 / 256, 256>>>(x, xc, XN4);
    dim3 tgrid(DD / 32, DD / 32);
    cvt_t_kernel<<<tgrid, 256>>>(Wq, wqc);
    cvt_t_kernel<<<tgrid, 256>>>(Wk, wkc);
    cvt_t_kernel<<<tgrid, 256>>>(Wv, wvc);
    cvt_t_kernel<<<tgrid, 256>>>(Wout, woc);

    cudaFuncSetAttribute(mma_gemm_kernel<0>, cudaFuncAttributeMaxDynamicSharedMemorySize,
                         GEMM_SMEM_BYTES);
    cudaFuncSetAttribute(mma_gemm_kernel<1>, cudaFuncAttributeMaxDynamicSharedMemorySize,
                         GEMM_SMEM_BYTES);
    cudaFuncSetAttribute(attn_mma_kernel, cudaFuncAttributeMaxDynamicSharedMemorySize,
                         ATTN2_BYTES);

    // fused QKV: grid.x = 48 (16 n-blocks x 3 matrices)
    mma_gemm_kernel<1><<<dim3(48, M / 128), 256, GEMM_SMEM_BYTES>>>(
        xc, wqc, wkc, wvc, qp, kp, vp, nullptr, M, DD, DD);

    const int rope_blocks = (BB * HH * LL) / 8;
    rope_norm_kernel<<<rope_blocks, 256>>>(qp);
    rope_norm_kernel<<<rope_blocks, 256>>>(kp);

    attn_mma_kernel<<<dim3(LL / 128, HH, BB), 256, ATTN2_BYTES>>>(scale);

    mma_gemm_kernel<0><<<dim3(16, M / 128), 256, GEMM_SMEM_BYTES>>>(
        ap, woc, nullptr, nullptr, nullptr, nullptr, nullptr, out, M, DD, DD);
}

// round 15
// speedup vs baseline: 1.4871x; 1.0144x over previous
#include <cuda_runtime.h>
#include <cstdint>
#include <cmath>

#define BB 2
#define LL 2048
#define DD 2048
#define HH 16
#define DH 128

// ---------------- scratch ----------------
__device__ float    g_q[(size_t)BB * HH * LL * DH];     // fp32 after GEMM, tf32 bits after rope
__device__ float    g_k[(size_t)BB * HH * LL * DH];
__device__ uint32_t g_v[(size_t)BB * HH * LL * DH];     // tf32 bits, TRANSPOSED: [b][h][d][l]
__device__ uint32_t g_attn[(size_t)BB * LL * DD];       // tf32 bits
__device__ uint32_t g_xc[(size_t)BB * LL * DD];         // x as tf32 bits
__device__ uint32_t g_wqc[(size_t)DD * DD];             // W^T as tf32 bits  [n][k]
__device__ uint32_t g_wkc[(size_t)DD * DD];
__device__ uint32_t g_wvc[(size_t)DD * DD];
__device__ uint32_t g_woc[(size_t)DD * DD];
__device__ float    g_invf[64];

__global__ void build_invf_kernel() {
    int i = threadIdx.x;
    if (i < 64) {
        double e = (double)(2 * i) / 128.0;
        g_invf[i] = (float)pow(500000.0, -e);
    }
}

__device__ __forceinline__ uint32_t smem_u32(const void* p) {
    uint32_t a;
    asm("{ .reg .u64 t; cvta.to.shared.u64 t, %1; cvt.u32.u64 %0, t; }"
        : "=r"(a) : "l"(p));
    return a;
}

__device__ __forceinline__ uint32_t f2tf32(float f) {
    uint32_t u;
    asm("cvt.rna.tf32.f32 %0, %1;" : "=r"(u) : "f"(f));
    return u;
}

__device__ __forceinline__ float fast_exp2(float x) {
    float r;
    asm("ex2.approx.ftz.f32 %0, %1;" : "=f"(r) : "f"(x));
    return r;
}

#define MMA_TF32(acc, a0, a1, a2, a3, b0, b1)                                 \
    asm volatile(                                                             \
        "mma.sync.aligned.m16n8k8.row.col.f32.tf32.tf32.f32 "                 \
        "{%0,%1,%2,%3}, {%4,%5,%6,%7}, {%8,%9}, {%0,%1,%2,%3};"               \
        : "+f"((acc)[0]), "+f"((acc)[1]), "+f"((acc)[2]), "+f"((acc)[3])      \
        : "r"(a0), "r"(a1), "r"(a2), "r"(a3), "r"(b0), "r"(b1))

#define LDSM_X4(r0, r1, r2, r3, addr)                                         \
    asm volatile("ldmatrix.sync.aligned.m8n8.x4.shared.b16 {%0,%1,%2,%3}, [%4];" \
                 : "=r"(r0), "=r"(r1), "=r"(r2), "=r"(r3) : "r"(addr))

#define CP_ASYNC16(saddr, gptr)                                               \
    asm volatile("cp.async.cg.shared.global [%0], [%1], 16;"                  \
                 :: "r"(saddr), "l"(gptr))
#define CP_COMMIT() asm volatile("cp.async.commit_group;")
#define CP_WAIT(n)  asm volatile("cp.async.wait_group %0;" :: "n"(n))

// ---------------- fp32 -> tf32-bits converters ----------------
__global__ __launch_bounds__(256)
void cvt_kernel(const float* __restrict__ s, uint32_t* __restrict__ d, int n4)
{
    int i = blockIdx.x * 256 + threadIdx.x;
    if (i < n4) {
        float4 v = ((const float4*)s)[i];
        ((uint4*)d)[i] = make_uint4(f2tf32(v.x), f2tf32(v.y), f2tf32(v.z), f2tf32(v.w));
    }
}

// transpose + convert, 4 matrices in one launch (blockIdx.z selects)
__global__ __launch_bounds__(256)
void cvt_t4_kernel(const float* __restrict__ s0, const float* __restrict__ s1,
                   const float* __restrict__ s2, const float* __restrict__ s3,
                   uint32_t* __restrict__ d0, uint32_t* __restrict__ d1,
                   uint32_t* __restrict__ d2, uint32_t* __restrict__ d3)
{
    __shared__ uint32_t tile[32][33];
    const int z = blockIdx.z;
    const float* s = (z == 0) ? s0 : (z == 1) ? s1 : (z == 2) ? s2 : s3;
    uint32_t* d = (z == 0) ? d0 : (z == 1) ? d1 : (z == 2) ? d2 : d3;
    const int tx = threadIdx.x & 31, ty = threadIdx.x >> 5;
    const int c0 = blockIdx.x * 32, r0 = blockIdx.y * 32;
#pragma unroll
    for (int i = 0; i < 4; i++)
        tile[ty + i * 8][tx] = f2tf32(s[(size_t)(r0 + ty + i * 8) * DD + c0 + tx]);
    __syncthreads();
#pragma unroll
    for (int i = 0; i < 4; i++)
        d[(size_t)(c0 + ty + i * 8) * DD + r0 + tx] = tile[tx][ty + i * 8];
}

// ============================================================================
// tf32 mma GEMM, ldmatrix feeds: C[M,N] = A[M,K] @ Bt^T  (Bt is [n][k])
// CTA 128x128, 8 warps (2m x 4n), warp 64x32.  3-stage cp.async pipeline.
// ============================================================================
#define ASTRIDE 36
#define A_FLOATS (128 * ASTRIDE)          // 4608
#define B_FLOATS (128 * ASTRIDE)          // 4608
#define BUF_FLOATS (A_FLOATS + B_FLOATS)  // 9216
#define GEMM_SMEM_BYTES (3 * BUF_FLOATS * 4)  // 110592

template <int MODE>
__global__ __launch_bounds__(256, 2)
void mma_gemm_kernel(const uint32_t* __restrict__ A,
                     const uint32_t* __restrict__ B0,
                     const uint32_t* __restrict__ B1,
                     const uint32_t* __restrict__ B2,
                     float* __restrict__ Cq, float* __restrict__ Ck,
                     uint32_t* __restrict__ Cv, float* __restrict__ Cout,
                     int M, int N, int K)
{
    extern __shared__ __align__(16) uint32_t smu[];
    const int tid = threadIdx.x;
    const int wid = tid >> 5;
    const int lane = tid & 31;
    const int warp_m = wid >> 2;       // 0..1
    const int warp_n = wid & 3;        // 0..3
    const int by = blockIdx.y;
    int bxm = blockIdx.x, mid = 0;
    const uint32_t* Bm;
    if (MODE == 1) {
        mid = bxm >> 4;
        bxm &= 15;
        Bm = (mid == 0) ? B0 : (mid == 1) ? B1 : B2;
    } else {
        Bm = B0;
    }
    const int m0 = by * 128, n0 = bxm * 128;
    const uint32_t sbase = smem_u32(smu);
    const int fr = lane >> 2, fc = lane & 3;
    const int t3 = lane >> 3, rr = lane & 7;

    const int a_row = warp_m * 64 + (t3 & 1) * 8 + rr;
    const int a_col = (t3 >> 1) * 4;
    const int b_row = warp_n * 32 + (t3 >> 1) * 8 + rr;
    const int b_col = (t3 & 1) * 4;

    const int l_r = tid >> 3, l_kq = tid & 7;
    const uint32_t* aG0 = A + (size_t)(m0 + l_r) * K + l_kq * 4;
    const uint32_t* bG0 = Bm + (size_t)(n0 + l_r) * K + l_kq * 4;
    const uint32_t aS0 = sbase + (uint32_t)(l_r * ASTRIDE + l_kq * 4) * 4;
    const uint32_t bS0 = sbase + (uint32_t)(A_FLOATS + l_r * ASTRIDE + l_kq * 4) * 4;

#define LOAD_TILE(kt, buf) do {                                               \
    const uint32_t off = (uint32_t)(buf) * (BUF_FLOATS * 4);                  \
    _Pragma("unroll")                                                         \
    for (int i = 0; i < 4; i++)                                               \
        CP_ASYNC16(aS0 + off + (uint32_t)(i * 32 * ASTRIDE) * 4,              \
                   aG0 + (size_t)(i * 32) * K + (kt) * 32);                   \
    _Pragma("unroll")                                                         \
    for (int i = 0; i < 4; i++)                                               \
        CP_ASYNC16(bS0 + off + (uint32_t)(i * 32 * ASTRIDE) * 4,              \
                   bG0 + (size_t)(i * 32) * K + (kt) * 32);                   \
    CP_COMMIT();                                                              \
} while (0)

    float acc[4][4][4];
#pragma unroll
    for (int mt = 0; mt < 4; mt++)
#pragma unroll
        for (int nt = 0; nt < 4; nt++)
#pragma unroll
            for (int r = 0; r < 4; r++) acc[mt][nt][r] = 0.f;

    const int KT = K / 32;
    LOAD_TILE(0, 0);
    LOAD_TILE(1, 1);

    int bufc = 0;
    for (int kt = 0; kt < KT; kt++) {
        if (kt + 1 < KT) CP_WAIT(1);
        else             CP_WAIT(0);
        __syncthreads();
        if (kt + 2 < KT) {
            int nb = bufc + 2; if (nb >= 3) nb -= 3;
            LOAD_TILE(kt + 2, nb);
        }

        const uint32_t sA = sbase + (uint32_t)bufc * (BUF_FLOATS * 4);
        const uint32_t sB = sA + A_FLOATS * 4;

#pragma unroll
        for (int s = 0; s < 4; s++) {
            const int kb = s * 8;
            uint32_t af[4][4], bf[4][2];
#pragma unroll
            for (int mt = 0; mt < 4; mt++)
                LDSM_X4(af[mt][0], af[mt][1], af[mt][2], af[mt][3],
                        sA + (uint32_t)((a_row + mt * 16) * ASTRIDE + kb + a_col) * 4);
            LDSM_X4(bf[0][0], bf[0][1], bf[1][0], bf[1][1],
                    sB + (uint32_t)(b_row * ASTRIDE + kb + b_col) * 4);
            LDSM_X4(bf[2][0], bf[2][1], bf[3][0], bf[3][1],
                    sB + (uint32_t)((b_row + 16) * ASTRIDE + kb + b_col) * 4);
#pragma unroll
            for (int mt = 0; mt < 4; mt++)
#pragma unroll
                for (int nt = 0; nt < 4; nt++)
                    MMA_TF32(acc[mt][nt], af[mt][0], af[mt][1], af[mt][2], af[mt][3],
                             bf[nt][0], bf[nt][1]);
        }
        bufc = bufc + 1; if (bufc == 3) bufc = 0;
    }

    // epilogue
#pragma unroll
    for (int mt = 0; mt < 4; mt++) {
#pragma unroll
        for (int nt = 0; nt < 4; nt++) {
            const int r0 = m0 + warp_m * 64 + mt * 16 + fr;
            const int nloc = warp_n * 32 + nt * 8 + fc * 2;
            float2 v0 = make_float2(acc[mt][nt][0], acc[mt][nt][1]);
            float2 v1 = make_float2(acc[mt][nt][2], acc[mt][nt][3]);
            if (MODE == 1) {
                const int b0_ = r0 >> 11, l0 = r0 & 2047;
                const int b1_ = (r0 + 8) >> 11, l1 = (r0 + 8) & 2047;
                if (mid == 2) {
                    const size_t vb0 = ((size_t)(b0_ * HH + bxm) * DH + nloc) * LL;
                    const size_t vb1 = ((size_t)(b1_ * HH + bxm) * DH + nloc) * LL;
                    Cv[vb0 + l0]      = f2tf32(v0.x);
                    Cv[vb0 + LL + l0] = f2tf32(v0.y);
                    Cv[vb1 + l1]      = f2tf32(v1.x);
                    Cv[vb1 + LL + l1] = f2tf32(v1.y);
                } else {
                    float* Ct = (mid == 0) ? Cq : Ck;
                    const size_t o0 = (((size_t)(b0_ * HH + bxm)) * LL + l0) * DH + nloc;
                    const size_t o1 = (((size_t)(b1_ * HH + bxm)) * LL + l1) * DH + nloc;
                    *(float2*)(Ct + o0) = v0;
                    *(float2*)(Ct + o1) = v1;
                }
            } else {
                *(float2*)(Cout + (size_t)r0 * N + n0 + nloc) = v0;
                *(float2*)(Cout + (size_t)(r0 + 8) * N + n0 + nloc) = v1;
            }
        }
    }
#undef LOAD_TILE
}

// ---------------- RoPE + L2-normalize; q and k in one launch ----------------
__global__ __launch_bounds__(256)
void rope_norm_kernel(float* __restrict__ tq, float* __restrict__ tk)
{
    const int gw = (blockIdx.x * 256 + threadIdx.x) >> 5;
    const int lane = threadIdx.x & 31;
    const int pos = gw & (LL - 1);
    float* row = (blockIdx.y ? tk : tq) + (size_t)gw * DH;

    const float invf0 = g_invf[lane];
    const float invf1 = g_invf[lane + 32];
    const float pf = (float)pos;
    float s0, c0, s1, c1;
    sincosf(pf * invf0, &s0, &c0);
    sincosf(pf * invf1, &s1, &c1);

    float2 x = ((const float2*)row)[lane];
    float2 y = ((const float2*)row)[lane + 32];
    const float r0 = x.x * c0 - x.y * s0;
    const float r1 = x.y * c0 + x.x * s0;
    const float r2 = y.x * c1 - y.y * s1;
    const float r3 = y.y * c1 + y.x * s1;

    float ss = r0 * r0 + r1 * r1 + r2 * r2 + r3 * r3;
#pragma unroll
    for (int off = 16; off > 0; off >>= 1)
        ss += __shfl_xor_sync(0xffffffffu, ss, off);
    const float inv = 1.0f / (sqrtf(ss) + 1e-6f);

    uint32_t* rowu = (uint32_t*)row;
    ((uint2*)rowu)[lane]      = make_uint2(f2tf32(r0 * inv), f2tf32(r1 * inv));
    ((uint2*)rowu)[lane + 32] = make_uint2(f2tf32(r2 * inv), f2tf32(r3 * inv));
}

// ============================================================================
// tensor-core causal flash attention, q-tile 128, 256 threads (8 warps x 16 q)
// MAX-FREE softmax fused into PV at 8-column granularity (EX2/STS overlap MMA).
// cp.async double-buffered K/V, one __syncthreads per k-tile.
// ============================================================================
#define AKS 132
#define AVS 68
#define APS 68
#define KBUF (64 * AKS)                    // 8448 u32 per K buffer
#define VBUF (128 * AVS)                   // 8704 u32 per V buffer
#define VB0 (2 * KBUF)                     // 16896
#define PB  (VB0 + 2 * VBUF)               // 34304
#define ATTN2_U32 (PB + 128 * APS)         // 43008
#define ATTN2_BYTES (ATTN2_U32 * 4)        // 172032

__global__ __launch_bounds__(256, 1)
void attn_mma_kernel(const float* __restrict__ scale_ptr)
{
    extern __shared__ __align__(16) uint32_t smu[];
    uint32_t* k_u = smu;                     // Q staging uses K buffer 0

    const int qt = (int)gridDim.x - 1 - (int)blockIdx.x;   // heavy tiles first
    const int h = blockIdx.y, b = blockIdx.z;
    const int tid = threadIdx.x;
    const int wid = tid >> 5, lane = tid & 31;
    const int fr = lane >> 2, fc = lane & 3;
    const int t3 = lane >> 3, rr = lane & 7;
    const float sc2 = (*scale_ptr) * 1.4426950408889634f;

    const size_t head_off = (size_t)(b * HH + h) * LL * DH;
    const uint32_t* qptr = (const uint32_t*)g_q + head_off;
    const uint32_t* kptr = (const uint32_t*)g_k + head_off;
    const uint32_t* vtptr = g_v + head_off;          // [d][l] layout
    const int q0 = qt * 128;

    const uint32_t sK = smem_u32(smu);
    const uint32_t sP = sK + (uint32_t)PB * 4;

    const int lr = tid >> 2, lq = tid & 3;           // K/Q loader: 64 rows, 4 thr/row
    const int vr = tid >> 1, vh = tid & 1;           // V loader: 128 rows, 2 thr/row

    const uint32_t kslot = (uint32_t)(lr * AKS + lq * 32) * 4;
    const uint32_t vslot = (uint32_t)(vr * AVS + vh * 32) * 4;
    const uint32_t kbufa[2] = {sK + kslot, sK + (uint32_t)KBUF * 4 + kslot};
    const uint32_t vbufa[2] = {sK + (uint32_t)VB0 * 4 + vslot,
                               sK + (uint32_t)(VB0 + VBUF) * 4 + vslot};

#define LOAD_KV(kt, bs) do {                                                  \
    const uint32_t* ksrc = kptr + (size_t)((kt) * 64 + lr) * DH + lq * 32;    \
    const uint32_t* vsrc = vtptr + (size_t)vr * LL + (kt) * 64 + vh * 32;     \
    _Pragma("unroll")                                                         \
    for (int j = 0; j < 8; j++)                                               \
        CP_ASYNC16(kbufa[bs] + (uint32_t)(j * 16), ksrc + j * 4);             \
    _Pragma("unroll")                                                         \
    for (int j = 0; j < 8; j++)                                               \
        CP_ASYNC16(vbufa[bs] + (uint32_t)(j * 16), vsrc + j * 4);             \
    CP_COMMIT();                                                              \
} while (0)

    // ---- stage Q bits (two 64-row passes through K buffer 0), preload A-frags ----
    uint32_t qa[16][4];
    const uint32_t qbase = sK +
        (uint32_t)(((wid & 3) * 16 + (t3 & 1) * 8 + rr) * AKS + (t3 >> 1) * 4) * 4;
    for (int pass = 0; pass < 2; pass++) {
        const uint32_t* src = qptr + (size_t)(q0 + pass * 64 + lr) * DH + lq * 32;
        uint32_t* dst = k_u + lr * AKS + lq * 32;
#pragma unroll
        for (int j = 0; j < 8; j++)
            *(uint4*)(dst + j * 4) = *(const uint4*)(src + j * 4);
        __syncthreads();
        if ((wid >> 2) == pass) {
#pragma unroll
            for (int s = 0; s < 16; s++)
                LDSM_X4(qa[s][0], qa[s][1], qa[s][2], qa[s][3],
                        qbase + (uint32_t)(s * 8) * 4);
        }
        __syncthreads();
    }

    float oacc[16][4];
#pragma unroll
    for (int nf = 0; nf < 16; nf++)
#pragma unroll
        for (int r = 0; r < 4; r++) oacc[nf][r] = 0.f;
    float l_[2] = {0.f, 0.f};

    const int row0 = q0 + wid * 16 + fr;

    // ldmatrix per-thread bases
    const int kb_row = (t3 >> 1) * 8 + rr;
    const int kb_col = (t3 & 1) * 4;
    const int vb_row = (t3 >> 1) * 8 + rr;
    const int vb_col = (t3 & 1) * 4;
    const int pa_row = wid * 16 + (t3 & 1) * 8 + rr;
    const int pa_col = (t3 >> 1) * 4;

    const int KTend = 2 * qt + 1;
    LOAD_KV(0, 0);
    int buf = 0;

    for (int kt = 0; kt <= KTend; kt++) {
        const int k0 = kt * 64;
        CP_WAIT(0);          // tile kt landed (only group in flight)
        __syncthreads();     // visibility + all warps done reading other buffer
        if (kt < KTend)
            LOAD_KV(kt + 1, buf ^ 1);   // overlaps with compute below

        const uint32_t sKb = sK + (buf ? (uint32_t)KBUF * 4 : 0u);
        const uint32_t sVb = sK + (buf ? (uint32_t)(VB0 + VBUF) * 4
                                       : (uint32_t)VB0 * 4);

        // ---- S = Q K^T ----
        float sacc[8][4];
#pragma unroll
        for (int j = 0; j < 8; j++)
#pragma unroll
            for (int r = 0; r < 4; r++) sacc[j][r] = 0.f;

#pragma unroll
        for (int s = 0; s < 16; s++) {
#pragma unroll
            for (int jj = 0; jj < 4; jj++) {
                uint32_t b0a, b1a, b0b, b1b;
                LDSM_X4(b0a, b1a, b0b, b1b,
                        sKb + (uint32_t)((jj * 16 + kb_row) * AKS + s * 8 + kb_col) * 4);
                MMA_TF32(sacc[2 * jj],     qa[s][0], qa[s][1], qa[s][2], qa[s][3], b0a, b1a);
                MMA_TF32(sacc[2 * jj + 1], qa[s][0], qa[s][1], qa[s][2], qa[s][3], b0b, b1b);
            }
        }

        // ---- mask (last two k-tiles straddle the diagonal) ----
        if (kt >= 2 * qt) {
#pragma unroll
            for (int j = 0; j < 8; j++) {
                const int c0 = k0 + 8 * j + 2 * fc;
                if (c0 > row0)     sacc[j][0] = -1e30f;
                if (c0 + 1 > row0) sacc[j][1] = -1e30f;
                if (c0 > row0 + 8)     sacc[j][2] = -1e30f;
                if (c0 + 1 > row0 + 8) sacc[j][3] = -1e30f;
            }
        }

        // ---- fused max-free softmax + PV, 8-column chunks:
        //      EX2/STS of chunk s2+1 overlap the tensor drain of chunk s2 ----
#pragma unroll
        for (int s2 = 0; s2 < 8; s2++) {
            float p00 = fast_exp2(sc2 * sacc[s2][0]);
            float p01 = fast_exp2(sc2 * sacc[s2][1]);
            float p10 = fast_exp2(sc2 * sacc[s2][2]);
            float p11 = fast_exp2(sc2 * sacc[s2][3]);
            l_[0] += p00 + p01;
            l_[1] += p10 + p11;
            uint32_t* prow0 = (uint32_t*)smu + PB + (wid * 16 + fr) * APS + 8 * s2 + 2 * fc;
            *(uint2*)prow0             = make_uint2(f2tf32(p00), f2tf32(p01));
            *(uint2*)(prow0 + 8 * APS) = make_uint2(f2tf32(p10), f2tf32(p11));
            __syncwarp();

            uint32_t a0, a1, a2, a3;
            LDSM_X4(a0, a1, a2, a3,
                    sP + (uint32_t)(pa_row * APS + s2 * 8 + pa_col) * 4);
#pragma unroll
            for (int nfp = 0; nfp < 8; nfp++) {
                uint32_t b0a, b1a, b0b, b1b;
                LDSM_X4(b0a, b1a, b0b, b1b,
                        sVb + (uint32_t)((nfp * 16 + vb_row) * AVS + s2 * 8 + vb_col) * 4);
                MMA_TF32(oacc[2 * nfp],     a0, a1, a2, a3, b0a, b1a);
                MMA_TF32(oacc[2 * nfp + 1], a0, a1, a2, a3, b0b, b1b);
            }
        }
        __syncwarp();
        buf ^= 1;
    }
#undef LOAD_KV

    // ---- reduce row sums across the quad ----
    float l0 = l_[0], l1 = l_[1];
    l0 += __shfl_xor_sync(0xffffffffu, l0, 1);
    l0 += __shfl_xor_sync(0xffffffffu, l0, 2);
    l1 += __shfl_xor_sync(0xffffffffu, l1, 1);
    l1 += __shfl_xor_sync(0xffffffffu, l1, 2);

    // ---- epilogue: normalize + write tf32 bits [b][l][h*128+d] ----
    const float inv0 = 1.f / l0;
    const float inv1 = 1.f / l1;
    uint32_t* d0p = g_attn + ((size_t)(b * LL + row0)) * DD + h * DH + 2 * fc;
    uint32_t* d1p = g_attn + ((size_t)(b * LL + row0 + 8)) * DD + h * DH + 2 * fc;
#pragma unroll
    for (int nf = 0; nf < 16; nf++) {
        *(uint2*)(d0p + 8 * nf) = make_uint2(f2tf32(oacc[nf][0] * inv0),
                                             f2tf32(oacc[nf][1] * inv0));
        *(uint2*)(d1p + 8 * nf) = make_uint2(f2tf32(oacc[nf][2] * inv1),
                                             f2tf32(oacc[nf][3] * inv1));
    }
}

// ---------------- launch ----------------
extern "C" void kernel_launch(void* const* d_in, const int* in_sizes, int n_in,
                              void* d_out, int out_size)
{
    const float* x     = (const float*)d_in[0];
    const float* Wq    = (const float*)d_in[1];
    const float* Wk    = (const float*)d_in[2];
    const float* Wv    = (const float*)d_in[3];
    const float* Wout  = (const float*)d_in[4];
    const float* scale = (const float*)d_in[5];
    float* out = (float*)d_out;

    float *qp, *kp;
    uint32_t *vp, *ap, *xc, *wqc, *wkc, *wvc, *woc;
    cudaGetSymbolAddress((void**)&qp,  g_q);
    cudaGetSymbolAddress((void**)&kp,  g_k);
    cudaGetSymbolAddress((void**)&vp,  g_v);
    cudaGetSymbolAddress((void**)&ap,  g_attn);
    cudaGetSymbolAddress((void**)&xc,  g_xc);
    cudaGetSymbolAddress((void**)&wqc, g_wqc);
    cudaGetSymbolAddress((void**)&wkc, g_wkc);
    cudaGetSymbolAddress((void**)&wvc, g_wvc);
    cudaGetSymbolAddress((void**)&woc, g_woc);

    build_invf_kernel<<<1, 64>>>();

    const int M = BB * LL;           // 4096
    const int XN4 = (M * DD) / 4;
    cvt_kernel<<<XN4 / 256, 256>>>(x, xc, XN4);
    dim3 tgrid(DD / 32, DD / 32, 4);
    cvt_t4_kernel<<<tgrid, 256>>>(Wq, Wk, Wv, Wout, wqc, wkc, wvc, woc);

    cudaFuncSetAttribute(mma_gemm_kernel<0>, cudaFuncAttributeMaxDynamicSharedMemorySize,
                         GEMM_SMEM_BYTES);
    cudaFuncSetAttribute(mma_gemm_kernel<1>, cudaFuncAttributeMaxDynamicSharedMemorySize,
                         GEMM_SMEM_BYTES);
    cudaFuncSetAttribute(attn_mma_kernel, cudaFuncAttributeMaxDynamicSharedMemorySize,
                         ATTN2_BYTES);

    // fused QKV: grid.x = 48 (16 n-blocks x 3 matrices)
    mma_gemm_kernel<1><<<dim3(48, M / 128), 256, GEMM_SMEM_BYTES>>>(
        xc, wqc, wkc, wvc, qp, kp, vp, nullptr, M, DD, DD);

    const int rope_blocks = (BB * HH * LL) / 8;
    rope_norm_kernel<<<dim3(rope_blocks, 2), 256>>>(qp, kp);

    attn_mma_kernel<<<dim3(LL / 128, HH, BB), 256, ATTN2_BYTES>>>(scale);

    mma_gemm_kernel<0><<<dim3(16, M / 128), 256, GEMM_SMEM_BYTES>>>(
        ap, woc, nullptr, nullptr, nullptr, nullptr, nullptr, out, M, DD, DD);
}